// round 6
// baseline (speedup 1.0000x reference)
#include <cuda_runtime.h>
#include <math.h>
#include <stdint.h>

#define BATCH 2
#define SQ 2048
#define NH 16
#define DK 64
#define DMODEL 1024
#define NREL 4095

__device__ float g_q[BATCH*NH*SQ*DK];
__device__ float g_k[BATCH*NH*SQ*DK];
__device__ float g_v[BATCH*NH*SQ*DK];
__device__ float g_ctx[(size_t)BATCH*SQ*DMODEL];
__device__ float g_bias[NH*NREL];

// ---------------------------------------------------------------------------
__device__ __forceinline__ float f2tf32(float x) {
    unsigned r;
    asm("cvt.rna.tf32.f32 %0, %1;" : "=r"(r) : "f"(x));
    return __uint_as_float(r);
}

__device__ __forceinline__ void mma_tf32(float c[4], const unsigned* a,
                                         const unsigned* b) {
    asm volatile(
        "mma.sync.aligned.m16n8k8.row.col.f32.tf32.tf32.f32 "
        "{%0,%1,%2,%3}, {%4,%5,%6,%7}, {%8,%9}, {%0,%1,%2,%3};\n"
        : "+f"(c[0]), "+f"(c[1]), "+f"(c[2]), "+f"(c[3])
        : "r"(a[0]), "r"(a[1]), "r"(a[2]), "r"(a[3]), "r"(b[0]), "r"(b[1]));
}

// Fragment-layout index helpers.
// A-side (mma A operand, 16-row blocks): block stride 132 words.
//   element (m,k): pos = (k&3)*8 + (m&7); word = ((m>>3)&1) + 2*((k>>2)&1)
// B-side (mma B operand, 8-col blocks): block stride 66 words.
//   element (n,k): pos = (k&3)*8 + (n&7); word = (k>>2)&1
template <int NKS>
__device__ __forceinline__ int aidx(int m, int k) {
    return ((m >> 4) * NKS + (k >> 3)) * 132 +
           ((k & 3) * 8 + (m & 7)) * 4 + ((m >> 3) & 1) + 2 * ((k >> 2) & 1);
}
template <int NKS>
__device__ __forceinline__ int bidx(int n, int k) {
    return ((n >> 3) * NKS + (k >> 3)) * 66 +
           ((k & 3) * 8 + (n & 7)) * 2 + ((k >> 2) & 1);
}

// ---------------------------------------------------------------------------
__global__ void bias_kernel(const float* __restrict__ emb) {
    int idx = blockIdx.x * blockDim.x + threadIdx.x;
    if (idx >= NREL) return;
    int rel = idx - (SQ - 1);
    int bucket = (rel > 0) ? 16 : 0;
    int rp = rel < 0 ? -rel : rel;
    int add;
    if (rp < 8) {
        add = rp;
    } else {
        float t = logf((float)rp * 0.125f);
        float u = t / 2.772588722239781f;
        float v = u * 8.0f;
        int w = 8 + (int)v;
        add = w < 15 ? w : 15;
    }
    bucket += add;
#pragma unroll
    for (int h = 0; h < NH; h++)
        g_bias[h * NREL + idx] = emb[bucket * NH + h];
}

// ---------------------------------------------------------------------------
// TF32 GEMM with fragment-layout SMEM. CTA 128x128, BK=16, 256 thr, 8 warps
// (2x4), warp tile 64x32. Double buffered, 1 sync/iter.
// ---------------------------------------------------------------------------
#define ASTG 2112   // 8 rowblks * 2 ks * 132
#define BSTG 2112   // 16 colblks * 2 ks * 66

template <int NSZ, int MODE>
__global__ __launch_bounds__(256)
void gemm_tc(const float* __restrict__ A, const float* __restrict__ B,
             float* __restrict__ Cout) {
    __shared__ __align__(16) float Af[2][ASTG];
    __shared__ __align__(16) float Bf[2][BSTG];

    const int n0 = blockIdx.x * 128;
    const int m0 = blockIdx.y * 128;
    const int tid = threadIdx.x;
    const int warp = tid >> 5, lane = tid & 31;
    const int wy = warp >> 2, wx = warp & 3;
    const int lpos4 = ((lane & 3) * 8 + (lane >> 2)) * 4;
    const int lpos2 = ((lane & 3) * 8 + (lane >> 2)) * 2;

    const float* Abase = (MODE == 0) ? A : (const float*)g_ctx;
    const float* Ap = Abase + (size_t)m0 * 1024;
    const float* Bp = B + n0;

    const int fa = 2 * tid;
    const int a_row0 = fa >> 2,       a_c0 = (fa & 3) * 4;
    const int a_row1 = (fa + 1) >> 2, a_c1 = ((fa + 1) & 3) * 4;
    const int b_row0 = fa >> 5,       b_c0 = (fa & 31) * 4;
    const int b_row1 = (fa + 1) >> 5, b_c1 = ((fa + 1) & 31) * 4;

    float acc[4][4][4];
#pragma unroll
    for (int i = 0; i < 4; i++)
#pragma unroll
        for (int j = 0; j < 4; j++)
#pragma unroll
            for (int r = 0; r < 4; r++) acc[i][j][r] = 0.f;

    float4 pa0, pa1, pb0, pb1;
    pa0 = *(const float4*)(Ap + (size_t)a_row0 * 1024 + a_c0);
    pa1 = *(const float4*)(Ap + (size_t)a_row1 * 1024 + a_c1);
    pb0 = *(const float4*)(Bp + (size_t)b_row0 * NSZ + b_c0);
    pb1 = *(const float4*)(Bp + (size_t)b_row1 * NSZ + b_c1);

#define STORE_STAGE(st)                                                     \
    do {                                                                    \
        float* as_ = Af[st]; float* bs_ = Bf[st];                           \
        const float* p0 = (const float*)&pa0;                               \
        const float* p1 = (const float*)&pa1;                               \
        const float* q0_ = (const float*)&pb0;                              \
        const float* q1_ = (const float*)&pb1;                              \
        _Pragma("unroll")                                                   \
        for (int j = 0; j < 4; j++) {                                       \
            as_[aidx<2>(a_row0, a_c0 + j)] = f2tf32(p0[j]);                 \
            as_[aidx<2>(a_row1, a_c1 + j)] = f2tf32(p1[j]);                 \
            bs_[bidx<2>(b_c0 + j, b_row0)] = f2tf32(q0_[j]);                \
            bs_[bidx<2>(b_c1 + j, b_row1)] = f2tf32(q1_[j]);                \
        }                                                                   \
    } while (0)

    STORE_STAGE(0);
    int s = 0;

    for (int k0 = 0; k0 < 1024; k0 += 16) {
        __syncthreads();
        const bool more = (k0 + 16 < 1024);
        if (more) {
            pa0 = *(const float4*)(Ap + (size_t)a_row0 * 1024 + k0 + 16 + a_c0);
            pa1 = *(const float4*)(Ap + (size_t)a_row1 * 1024 + k0 + 16 + a_c1);
            pb0 = *(const float4*)(Bp + (size_t)(k0 + 16 + b_row0) * NSZ + b_c0);
            pb1 = *(const float4*)(Bp + (size_t)(k0 + 16 + b_row1) * NSZ + b_c1);
        }
        const float* as = Af[s];
        const float* bs = Bf[s];
#pragma unroll
        for (int ks = 0; ks < 2; ks++) {
            uint4 af4[4];
            uint2 bf2[4];
#pragma unroll
            for (int mt = 0; mt < 4; mt++)
                af4[mt] = *(const uint4*)(as + ((wy * 4 + mt) * 2 + ks) * 132 + lpos4);
#pragma unroll
            for (int nt = 0; nt < 4; nt++)
                bf2[nt] = *(const uint2*)(bs + ((wx * 4 + nt) * 2 + ks) * 66 + lpos2);
#pragma unroll
            for (int mt = 0; mt < 4; mt++)
#pragma unroll
                for (int nt = 0; nt < 4; nt++)
                    mma_tf32(acc[mt][nt], (const unsigned*)&af4[mt],
                             (const unsigned*)&bf2[nt]);
        }
        if (more) STORE_STAGE(s ^ 1);
        s ^= 1;
    }
#undef STORE_STAGE

    const int lr = lane >> 2, lc = lane & 3;
#pragma unroll
    for (int mt = 0; mt < 4; mt++) {
        int gm0 = m0 + wy * 64 + mt * 16 + lr;
#pragma unroll
        for (int nt = 0; nt < 4; nt++) {
            int gn = n0 + wx * 32 + nt * 8 + 2 * lc;
            if (MODE == 1) {
                *(float2*)(Cout + (size_t)gm0 * NSZ + gn) =
                    make_float2(acc[mt][nt][0], acc[mt][nt][1]);
                *(float2*)(Cout + (size_t)(gm0 + 8) * NSZ + gn) =
                    make_float2(acc[mt][nt][2], acc[mt][nt][3]);
            } else {
                const int part = gn >> 10;
                const int h = (gn & 1023) >> 6;
                const int d = gn & 63;
                float* dst = (part == 0) ? g_q : (part == 1) ? g_k : g_v;
                {
                    int b = gm0 >> 11, sq = gm0 & 2047;
                    float* row = dst + ((size_t)((b * NH + h) * SQ) + sq) * DK;
                    *(float2*)(row + d) = make_float2(acc[mt][nt][0], acc[mt][nt][1]);
                }
                {
                    int gm1 = gm0 + 8;
                    int b = gm1 >> 11, sq = gm1 & 2047;
                    float* row = dst + ((size_t)((b * NH + h) * SQ) + sq) * DK;
                    *(float2*)(row + d) = make_float2(acc[mt][nt][2], acc[mt][nt][3]);
                }
            }
        }
    }
}

// ---------------------------------------------------------------------------
// Flash attention BQ=128, BKV=64, fragment-layout SMEM for Q/K/V.
// ---------------------------------------------------------------------------
#define BQ 128
#define BKV 64
#define QFSZ 8448   // 8 rowblks * 8 ks * 132
#define KFSZ 4224   // 8 colblks * 8 ks * 66
#define VFSZ 4224

__global__ __launch_bounds__(256)
void attn_tc(const float* __restrict__ mask) {
    extern __shared__ __align__(16) float sm[];
    float* Qf  = sm;
    float* Kf  = Qf + QFSZ;
    float* Vf  = Kf + KFSZ;
    float* Bsm = Vf + VFSZ;

    const int q0 = blockIdx.x * BQ;
    const int h  = blockIdx.y;
    const int b  = blockIdx.z;
    const int tid = threadIdx.x;
    const int warp = tid >> 5, lane = tid & 31;
    const int lr = lane >> 2, lc = lane & 3;
    const int r0 = warp * 16 + lr;
    const int r1 = r0 + 8;
    const int lpos4 = (lc * 8 + lr) * 4;
    const int lpos2 = (lc * 8 + lr) * 2;

    const float* Qg = g_q + ((size_t)(b * NH + h) * SQ + q0) * DK;
    const float* Kg = g_k + (size_t)(b * NH + h) * SQ * DK;
    const float* Vg = g_v + (size_t)(b * NH + h) * SQ * DK;
    const float* Mg = mask + (size_t)b * SQ * SQ;
    const float* Bg = g_bias + h * NREL;

    // Q tile -> fragment layout
#pragma unroll
    for (int t = 0; t < 8; t++) {
        int f = tid + t * 256;
        int r = f >> 4, c4 = (f & 15) * 4;
        float4 v = *(const float4*)(Qg + r * DK + c4);
        const float* pv = (const float*)&v;
#pragma unroll
        for (int j = 0; j < 4; j++)
            Qf[aidx<8>(r, c4 + j)] = f2tf32(pv[j]);
    }

    float m0 = -3.0e38f, m1 = -3.0e38f, l0 = 0.f, l1 = 0.f;
    float o[8][4];
#pragma unroll
    for (int nt = 0; nt < 8; nt++)
#pragma unroll
        for (int r = 0; r < 4; r++) o[nt][r] = 0.f;

    const unsigned FULL = 0xffffffffu;
    const int src0 = (lane & 28) | (lc >> 1);
    const int src1 = src0 + 2;
    const bool odd = (lc & 1) != 0;

    for (int k0 = 0; k0 < SQ; k0 += BKV) {
        __syncthreads();
        // K, V -> fragment layouts
#pragma unroll
        for (int t = 0; t < 4; t++) {
            int f = tid + t * 256;
            int r = f >> 4, c4 = (f & 15) * 4;
            float4 kv = *(const float4*)(Kg + (size_t)(k0 + r) * DK + c4);
            float4 vv = *(const float4*)(Vg + (size_t)(k0 + r) * DK + c4);
            const float* pk = (const float*)&kv;
            const float* pvv = (const float*)&vv;
#pragma unroll
            for (int j = 0; j < 4; j++) {
                Kf[bidx<8>(r, c4 + j)] = f2tf32(pk[j]);     // K[key=r][d]
                Vf[bidx<8>(c4 + j, r)] = f2tf32(pvv[j]);    // V[kk=r][d]: n=d,k=kk
            }
        }
        if (tid < 191)
            Bsm[tid] = Bg[k0 - q0 + tid - 127 + (SQ - 1)];
        __syncthreads();

        // S = Q K^T
        float sc[8][4];
#pragma unroll
        for (int nt = 0; nt < 8; nt++)
#pragma unroll
            for (int r = 0; r < 4; r++) sc[nt][r] = 0.f;

#pragma unroll
        for (int ks = 0; ks < 8; ks++) {
            uint4 a4 = *(const uint4*)(Qf + (warp * 8 + ks) * 132 + lpos4);
#pragma unroll
            for (int nt = 0; nt < 8; nt++) {
                uint2 b2 = *(const uint2*)(Kf + (nt * 8 + ks) * 66 + lpos2);
                mma_tf32(sc[nt], (const unsigned*)&a4, (const unsigned*)&b2);
            }
        }

        // scale + mask + bias
        {
            int gq0 = q0 + r0, gq1 = q0 + r1;
#pragma unroll
            for (int nt = 0; nt < 8; nt++) {
                int col = nt * 8 + 2 * lc;
                int kg = k0 + col;
                float2 mv0 = *(const float2*)(Mg + (size_t)gq0 * SQ + kg);
                float2 mv1 = *(const float2*)(Mg + (size_t)gq1 * SQ + kg);
                float b00 = Bsm[col - r0 + 127];
                float b01 = Bsm[col + 1 - r0 + 127];
                float b10 = Bsm[col - r1 + 127];
                float b11 = Bsm[col + 1 - r1 + 127];
                sc[nt][0] = sc[nt][0] * 0.125f * mv0.x + (b00 - 10000.f * (1.f - mv0.x));
                sc[nt][1] = sc[nt][1] * 0.125f * mv0.y + (b01 - 10000.f * (1.f - mv0.y));
                sc[nt][2] = sc[nt][2] * 0.125f * mv1.x + (b10 - 10000.f * (1.f - mv1.x));
                sc[nt][3] = sc[nt][3] * 0.125f * mv1.y + (b11 - 10000.f * (1.f - mv1.y));
            }
        }

        // Online softmax in registers
        float tm0 = -3.0e38f, tm1 = -3.0e38f;
#pragma unroll
        for (int nt = 0; nt < 8; nt++) {
            tm0 = fmaxf(tm0, fmaxf(sc[nt][0], sc[nt][1]));
            tm1 = fmaxf(tm1, fmaxf(sc[nt][2], sc[nt][3]));
        }
        tm0 = fmaxf(tm0, __shfl_xor_sync(FULL, tm0, 1));
        tm0 = fmaxf(tm0, __shfl_xor_sync(FULL, tm0, 2));
        tm1 = fmaxf(tm1, __shfl_xor_sync(FULL, tm1, 1));
        tm1 = fmaxf(tm1, __shfl_xor_sync(FULL, tm1, 2));
        float mn0 = fmaxf(m0, tm0), mn1 = fmaxf(m1, tm1);
        float al0 = __expf(m0 - mn0), al1 = __expf(m1 - mn1);
        m0 = mn0; m1 = mn1;
        float ps0 = 0.f, ps1 = 0.f;
#pragma unroll
        for (int nt = 0; nt < 8; nt++) {
            float e0 = __expf(sc[nt][0] - mn0);
            float e1 = __expf(sc[nt][1] - mn0);
            float e2 = __expf(sc[nt][2] - mn1);
            float e3 = __expf(sc[nt][3] - mn1);
            ps0 += e0 + e1; ps1 += e2 + e3;
            sc[nt][0] = f2tf32(e0); sc[nt][1] = f2tf32(e1);
            sc[nt][2] = f2tf32(e2); sc[nt][3] = f2tf32(e3);
        }
        ps0 += __shfl_xor_sync(FULL, ps0, 1);
        ps0 += __shfl_xor_sync(FULL, ps0, 2);
        ps1 += __shfl_xor_sync(FULL, ps1, 1);
        ps1 += __shfl_xor_sync(FULL, ps1, 2);
        l0 = l0 * al0 + ps0;
        l1 = l1 * al1 + ps1;

#pragma unroll
        for (int nt = 0; nt < 8; nt++) {
            o[nt][0] *= al0; o[nt][1] *= al0;
            o[nt][2] *= al1; o[nt][3] *= al1;
        }

        // O += P V (P C-frag -> A-frag by shuffles)
#pragma unroll
        for (int ks = 0; ks < 8; ks++) {
            float t00 = __shfl_sync(FULL, sc[ks][0], src0);
            float t01 = __shfl_sync(FULL, sc[ks][1], src0);
            float t10 = __shfl_sync(FULL, sc[ks][2], src0);
            float t11 = __shfl_sync(FULL, sc[ks][3], src0);
            float u00 = __shfl_sync(FULL, sc[ks][0], src1);
            float u01 = __shfl_sync(FULL, sc[ks][1], src1);
            float u10 = __shfl_sync(FULL, sc[ks][2], src1);
            float u11 = __shfl_sync(FULL, sc[ks][3], src1);
            unsigned af[4];
            af[0] = __float_as_uint(odd ? t01 : t00);
            af[1] = __float_as_uint(odd ? t11 : t10);
            af[2] = __float_as_uint(odd ? u01 : u00);
            af[3] = __float_as_uint(odd ? u11 : u10);
#pragma unroll
            for (int nt = 0; nt < 8; nt++) {
                uint2 b2 = *(const uint2*)(Vf + (nt * 8 + ks) * 66 + lpos2);
                mma_tf32(o[nt], af, (const unsigned*)&b2);
            }
        }
    }

    // Finalize
    {
        float li0 = 1.0f / l0, li1 = 1.0f / l1;
        int gq0 = q0 + r0, gq1 = q0 + r1;
#pragma unroll
        for (int nt = 0; nt < 8; nt++) {
            int d = h * DK + nt * 8 + 2 * lc;
            *(float2*)(g_ctx + (size_t)(b * SQ + gq0) * DMODEL + d) =
                make_float2(f2tf32(o[nt][0] * li0), f2tf32(o[nt][1] * li0));
            *(float2*)(g_ctx + (size_t)(b * SQ + gq1) * DMODEL + d) =
                make_float2(f2tf32(o[nt][2] * li1), f2tf32(o[nt][3] * li1));
        }
    }
}

// ---------------------------------------------------------------------------
extern "C" void kernel_launch(void* const* d_in, const int* in_sizes, int n_in,
                              void* d_out, int out_size) {
    (void)in_sizes; (void)n_in; (void)out_size;
    const float* hidden = (const float*)d_in[0];
    const float* mask   = (const float*)d_in[1];
    const float* Wqkv   = (const float*)d_in[2];
    const float* Wo     = (const float*)d_in[3];
    const float* emb    = (const float*)d_in[4];
    float* out = (float*)d_out;

    bias_kernel<<<16, 256>>>(emb);

    gemm_tc<3072, 0><<<dim3(24, 32), 256>>>(hidden, Wqkv, nullptr);

    const int smem_bytes = (QFSZ + KFSZ + VFSZ + 192) * 4;  // 68352
    cudaFuncSetAttribute(attn_tc, cudaFuncAttributeMaxDynamicSharedMemorySize,
                         smem_bytes);
    attn_tc<<<dim3(SQ / BQ, NH, BATCH), 256, smem_bytes>>>(mask);

    gemm_tc<1024, 1><<<dim3(8, 32), 256>>>(nullptr, Wo, out);
}

// round 9
// speedup vs baseline: 1.4643x; 1.4643x over previous
#include <cuda_runtime.h>
#include <math.h>
#include <stdint.h>

#define BATCH 2
#define SQ 2048
#define NH 16
#define DK 64
#define DMODEL 1024
#define NREL 4095

__device__ float g_q[BATCH*NH*SQ*DK];
__device__ float g_k[BATCH*NH*SQ*DK];
__device__ float g_v[BATCH*NH*SQ*DK];
__device__ float g_ctx[(size_t)BATCH*SQ*DMODEL];
__device__ float g_bias[NH*NREL];
__device__ float g_hid[(size_t)BATCH*SQ*DMODEL];
__device__ float g_wqkv_r[DMODEL*3*DMODEL];
__device__ float g_wo_r[DMODEL*DMODEL];

// ---------------------------------------------------------------------------
__device__ __forceinline__ float f2tf32(float x) {
    unsigned r;
    asm("cvt.rna.tf32.f32 %0, %1;" : "=r"(r) : "f"(x));
    return __uint_as_float(r);
}

__device__ __forceinline__ void mma_tf32(float c[4], const unsigned* a,
                                         const unsigned* b) {
    asm volatile(
        "mma.sync.aligned.m16n8k8.row.col.f32.tf32.tf32.f32 "
        "{%0,%1,%2,%3}, {%4,%5,%6,%7}, {%8,%9}, {%0,%1,%2,%3};\n"
        : "+f"(c[0]), "+f"(c[1]), "+f"(c[2]), "+f"(c[3])
        : "r"(a[0]), "r"(a[1]), "r"(a[2]), "r"(a[3]), "r"(b[0]), "r"(b[1]));
}

__device__ __forceinline__ uint32_t s2u(const void* p) {
    uint32_t a;
    asm("{ .reg .u64 t; cvta.to.shared.u64 t, %1; cvt.u32.u64 %0, t; }"
        : "=r"(a) : "l"(p));
    return a;
}
__device__ __forceinline__ void cpa16(uint32_t dst, const void* src) {
    asm volatile("cp.async.ca.shared.global [%0], [%1], 16;"
                 :: "r"(dst), "l"(src));
}
__device__ __forceinline__ void cpa_commit() {
    asm volatile("cp.async.commit_group;" ::: "memory");
}
template <int N>
__device__ __forceinline__ void cpa_wait() {
    asm volatile("cp.async.wait_group %0;" :: "n"(N) : "memory");
}

// ---------------------------------------------------------------------------
__global__ void bias_kernel(const float* __restrict__ emb) {
    int idx = blockIdx.x * blockDim.x + threadIdx.x;
    if (idx >= NREL) return;
    int rel = idx - (SQ - 1);
    int bucket = (rel > 0) ? 16 : 0;
    int rp = rel < 0 ? -rel : rel;
    int add;
    if (rp < 8) {
        add = rp;
    } else {
        float t = logf((float)rp * 0.125f);
        float u = t / 2.772588722239781f;
        float v = u * 8.0f;
        int w = 8 + (int)v;
        add = w < 15 ? w : 15;
    }
    bucket += add;
#pragma unroll
    for (int h = 0; h < NH; h++)
        g_bias[h * NREL + idx] = emb[bucket * NH + h];
}

// Round input to tf32 and store into a __device__ global selected in DEVICE
// code (host code must never reference device globals directly).
template <int WHICH>
__global__ void round_to(const float* __restrict__ src) {
    float* dst = (WHICH == 0) ? g_hid : (WHICH == 1) ? g_wqkv_r : g_wo_r;
    size_t idx = (size_t)blockIdx.x * blockDim.x + threadIdx.x;
    float4 v = *(const float4*)(src + idx * 4);
    v.x = f2tf32(v.x); v.y = f2tf32(v.y); v.z = f2tf32(v.z); v.w = f2tf32(v.w);
    *(float4*)(dst + idx * 4) = v;
}

// ---------------------------------------------------------------------------
// TF32 GEMM, 3-stage cp.async pipeline. CTA 128x128, BK=16, 256 thr,
// 8 warps (2x4), warp tile 64x32. Inputs pre-rounded to tf32.
// ---------------------------------------------------------------------------
#define AP 20
#define BP 136
#define ASW (128 * AP)   // 2560 words / stage
#define BSW (16 * BP)    // 2176 words / stage

template <int NSZ, int MODE>
__global__ __launch_bounds__(256)
void gemm_tc(float* __restrict__ Cout) {
    extern __shared__ __align__(16) float smf[];
    const uint32_t sb = s2u(smf);

    const int n0 = blockIdx.x * 128;
    const int m0 = blockIdx.y * 128;
    const int tid = threadIdx.x;
    const int warp = tid >> 5, lane = tid & 31;
    const int wy = warp >> 2, wx = warp & 3;
    const int lr = lane >> 2, lc = lane & 3;

    const float* Ap = ((MODE == 0) ? g_hid : (const float*)g_ctx) + (size_t)m0 * 1024;
    const float* Bp = ((MODE == 0) ? g_wqkv_r : g_wo_r) + n0;

    const int fa = 2 * tid;
    const int a_row0 = fa >> 2,       a_c0 = (fa & 3) * 4;
    const int a_row1 = (fa + 1) >> 2, a_c1 = ((fa + 1) & 3) * 4;
    const int b_row0 = fa >> 5,       b_c0 = (fa & 31) * 4;
    const int b_row1 = (fa + 1) >> 5, b_c1 = ((fa + 1) & 31) * 4;

    const uint32_t adst0 = sb + (a_row0 * AP + a_c0) * 4;
    const uint32_t adst1 = sb + (a_row1 * AP + a_c1) * 4;
    const uint32_t bdst0 = sb + (3 * ASW + b_row0 * BP + b_c0) * 4;
    const uint32_t bdst1 = sb + (3 * ASW + b_row1 * BP + b_c1) * 4;

    float acc[4][4][4];
#pragma unroll
    for (int i = 0; i < 4; i++)
#pragma unroll
        for (int j = 0; j < 4; j++)
#pragma unroll
            for (int r = 0; r < 4; r++) acc[i][j][r] = 0.f;

#define ISSUE(st, kt)                                                        \
    do {                                                                     \
        cpa16(adst0 + (st) * ASW * 4, Ap + (size_t)a_row0 * 1024 + (kt) * 16 + a_c0); \
        cpa16(adst1 + (st) * ASW * 4, Ap + (size_t)a_row1 * 1024 + (kt) * 16 + a_c1); \
        cpa16(bdst0 + (st) * BSW * 4, Bp + (size_t)((kt) * 16 + b_row0) * NSZ + b_c0); \
        cpa16(bdst1 + (st) * BSW * 4, Bp + (size_t)((kt) * 16 + b_row1) * NSZ + b_c1); \
    } while (0)

    ISSUE(0, 0); cpa_commit();
    ISSUE(1, 1); cpa_commit();

    int s = 0;
    for (int it = 0; it < 64; it++) {
        cpa_wait<1>();
        __syncthreads();
        if (it + 2 < 64) ISSUE((it + 2) % 3, it + 2);
        cpa_commit();

        const float* as = smf + s * ASW;
        const float* bs = smf + 3 * ASW + s * BSW;
#pragma unroll
        for (int ks = 0; ks < 2; ks++) {
            unsigned af[4][4], bf[4][2];
#pragma unroll
            for (int mt = 0; mt < 4; mt++) {
                int r0 = wy * 64 + mt * 16 + lr;
                af[mt][0] = __float_as_uint(as[r0 * AP + ks * 8 + lc]);
                af[mt][1] = __float_as_uint(as[(r0 + 8) * AP + ks * 8 + lc]);
                af[mt][2] = __float_as_uint(as[r0 * AP + ks * 8 + lc + 4]);
                af[mt][3] = __float_as_uint(as[(r0 + 8) * AP + ks * 8 + lc + 4]);
            }
#pragma unroll
            for (int nt = 0; nt < 4; nt++) {
                int n = wx * 32 + nt * 8 + lr;
                bf[nt][0] = __float_as_uint(bs[(ks * 8 + lc) * BP + n]);
                bf[nt][1] = __float_as_uint(bs[(ks * 8 + lc + 4) * BP + n]);
            }
#pragma unroll
            for (int mt = 0; mt < 4; mt++)
#pragma unroll
                for (int nt = 0; nt < 4; nt++)
                    mma_tf32(acc[mt][nt], af[mt], bf[nt]);
        }
        s = (s + 1) % 3;
    }
#undef ISSUE

#pragma unroll
    for (int mt = 0; mt < 4; mt++) {
        int gm0 = m0 + wy * 64 + mt * 16 + lr;
#pragma unroll
        for (int nt = 0; nt < 4; nt++) {
            int gn = n0 + wx * 32 + nt * 8 + 2 * lc;
            if (MODE == 1) {
                *(float2*)(Cout + (size_t)gm0 * NSZ + gn) =
                    make_float2(acc[mt][nt][0], acc[mt][nt][1]);
                *(float2*)(Cout + (size_t)(gm0 + 8) * NSZ + gn) =
                    make_float2(acc[mt][nt][2], acc[mt][nt][3]);
            } else {
                const int part = gn >> 10;
                const int h = (gn & 1023) >> 6;
                const int d = gn & 63;
                float* dst = (part == 0) ? g_q : (part == 1) ? g_k : g_v;
                {
                    int b = gm0 >> 11, sq = gm0 & 2047;
                    float* row = dst + ((size_t)((b * NH + h) * SQ) + sq) * DK;
                    *(float2*)(row + d) =
                        make_float2(f2tf32(acc[mt][nt][0]), f2tf32(acc[mt][nt][1]));
                }
                {
                    int gm1 = gm0 + 8;
                    int b = gm1 >> 11, sq = gm1 & 2047;
                    float* row = dst + ((size_t)((b * NH + h) * SQ) + sq) * DK;
                    *(float2*)(row + d) =
                        make_float2(f2tf32(acc[mt][nt][2]), f2tf32(acc[mt][nt][3]));
                }
            }
        }
    }
}

// ---------------------------------------------------------------------------
// Flash attention: BQ=128, BKV=32, double-buffered K/V via cp.async.
// q/k/v pre-rounded to tf32 by the QKV GEMM epilogue.
// ---------------------------------------------------------------------------
#define BQ 128
#define BKV 32
#define QP 68
#define KP 68
#define VP 72
#define QW (BQ * QP)            // 8704
#define KW (BKV * KP)           // 2176 per stage
#define VW (BKV * VP)           // 2304 per stage
#define KOFF QW                 // 8704
#define VOFF (QW + 2 * KW)      // 13056
#define BOFF (VOFF + 2 * VW)    // 17664
#define TOTW (BOFF + 2 * 160)   // 17984 words = 71936 B

__global__ __launch_bounds__(256)
void attn_tc(const float* __restrict__ mask) {
    extern __shared__ __align__(16) float sm[];
    const uint32_t sb = s2u(sm);

    const int q0 = blockIdx.x * BQ;
    const int h  = blockIdx.y;
    const int b  = blockIdx.z;
    const int tid = threadIdx.x;
    const int warp = tid >> 5, lane = tid & 31;
    const int lr = lane >> 2, lc = lane & 3;
    const int r0 = warp * 16 + lr;
    const int r1 = r0 + 8;

    const float* Qg = g_q + ((size_t)(b * NH + h) * SQ + q0) * DK;
    const float* Kg = g_k + (size_t)(b * NH + h) * SQ * DK;
    const float* Vg = g_v + (size_t)(b * NH + h) * SQ * DK;
    const float* Mg = mask + (size_t)b * SQ * SQ;
    const float* Bg = g_bias + h * NREL;

    // K/V loader: 128 threads per tensor; each thread copies 16 floats
    // (4 x cp.async.16B). 32 rows x 16 chunks = 512 chunks per tensor.
    const int kvr = (tid & 127) >> 2;          // row 0..31
    const int kvc = (tid & 3) * 16;            // col base in floats (0,16,32,48)
    const bool isK = tid < 128;

#define ISSUE_KV(st, t)                                                       \
    do {                                                                      \
        if (isK) {                                                            \
            const float* srcp = Kg + (size_t)((t) * BKV + kvr) * DK + kvc;    \
            uint32_t dstp = sb + (KOFF + (st) * KW + kvr * KP + kvc) * 4;     \
            cpa16(dstp,      srcp);                                           \
            cpa16(dstp + 16, srcp + 4);                                       \
            cpa16(dstp + 32, srcp + 8);                                       \
            cpa16(dstp + 48, srcp + 12);                                      \
        } else {                                                              \
            const float* srcp = Vg + (size_t)((t) * BKV + kvr) * DK + kvc;    \
            uint32_t dstp = sb + (VOFF + (st) * VW + kvr * VP + kvc) * 4;     \
            cpa16(dstp,      srcp);                                           \
            cpa16(dstp + 16, srcp + 4);                                       \
            cpa16(dstp + 32, srcp + 8);                                       \
            cpa16(dstp + 48, srcp + 12);                                      \
        }                                                                     \
    } while (0)

    // Prologue: Q + tile0 K/V + bias0
#pragma unroll
    for (int t = 0; t < 8; t++) {
        int f = tid + t * 256;
        int r = f >> 4, c4 = (f & 15) * 4;
        cpa16(sb + (r * QP + c4) * 4, Qg + r * DK + c4);
    }
    ISSUE_KV(0, 0);
    cpa_commit();
    if (tid < 159) sm[BOFF + tid] = Bg[-q0 + tid + 1920];

    float m0 = -3.0e38f, m1 = -3.0e38f, l0 = 0.f, l1 = 0.f;
    float o[8][4];
#pragma unroll
    for (int nt = 0; nt < 8; nt++)
#pragma unroll
        for (int r = 0; r < 4; r++) o[nt][r] = 0.f;

    const unsigned FULL = 0xffffffffu;
    const int src0 = (lane & 28) | (lc >> 1);
    const int src1 = src0 + 2;
    const bool odd = (lc & 1) != 0;

    for (int it = 0; it < SQ / BKV; it++) {
        const int s = it & 1;
        cpa_wait<0>();
        __syncthreads();
        if (it + 1 < SQ / BKV) {
            ISSUE_KV(s ^ 1, it + 1);
            if (tid < 159)
                sm[BOFF + (s ^ 1) * 160 + tid] = Bg[(it + 1) * BKV - q0 + tid + 1920];
        }
        cpa_commit();

        const float* Ks = sm + KOFF + s * KW;
        const float* Vs = sm + VOFF + s * VW;
        const float* Bs = sm + BOFF + s * 160;
        const int k0 = it * BKV;

        // S = Q K^T (16x32 per warp)
        float sc[4][4];
#pragma unroll
        for (int nt = 0; nt < 4; nt++)
#pragma unroll
            for (int r = 0; r < 4; r++) sc[nt][r] = 0.f;

#pragma unroll
        for (int ks = 0; ks < 8; ks++) {
            unsigned af[4], bf[4][2];
            af[0] = __float_as_uint(sm[r0 * QP + ks * 8 + lc]);
            af[1] = __float_as_uint(sm[r1 * QP + ks * 8 + lc]);
            af[2] = __float_as_uint(sm[r0 * QP + ks * 8 + lc + 4]);
            af[3] = __float_as_uint(sm[r1 * QP + ks * 8 + lc + 4]);
#pragma unroll
            for (int nt = 0; nt < 4; nt++) {
                int key = nt * 8 + lr;
                bf[nt][0] = __float_as_uint(Ks[key * KP + ks * 8 + lc]);
                bf[nt][1] = __float_as_uint(Ks[key * KP + ks * 8 + lc + 4]);
            }
#pragma unroll
            for (int nt = 0; nt < 4; nt++)
                mma_tf32(sc[nt], af, bf[nt]);
        }

        // scale + mask + bias
        {
            int gq0 = q0 + r0, gq1 = q0 + r1;
#pragma unroll
            for (int nt = 0; nt < 4; nt++) {
                int col = nt * 8 + 2 * lc;
                int kg = k0 + col;
                float2 mv0 = *(const float2*)(Mg + (size_t)gq0 * SQ + kg);
                float2 mv1 = *(const float2*)(Mg + (size_t)gq1 * SQ + kg);
                float b00 = Bs[col - r0 + 127];
                float b01 = Bs[col + 1 - r0 + 127];
                float b10 = Bs[col - r1 + 127];
                float b11 = Bs[col + 1 - r1 + 127];
                sc[nt][0] = sc[nt][0] * 0.125f * mv0.x + (b00 - 10000.f * (1.f - mv0.x));
                sc[nt][1] = sc[nt][1] * 0.125f * mv0.y + (b01 - 10000.f * (1.f - mv0.y));
                sc[nt][2] = sc[nt][2] * 0.125f * mv1.x + (b10 - 10000.f * (1.f - mv1.x));
                sc[nt][3] = sc[nt][3] * 0.125f * mv1.y + (b11 - 10000.f * (1.f - mv1.y));
            }
        }

        // Online softmax
        float tm0 = -3.0e38f, tm1 = -3.0e38f;
#pragma unroll
        for (int nt = 0; nt < 4; nt++) {
            tm0 = fmaxf(tm0, fmaxf(sc[nt][0], sc[nt][1]));
            tm1 = fmaxf(tm1, fmaxf(sc[nt][2], sc[nt][3]));
        }
        tm0 = fmaxf(tm0, __shfl_xor_sync(FULL, tm0, 1));
        tm0 = fmaxf(tm0, __shfl_xor_sync(FULL, tm0, 2));
        tm1 = fmaxf(tm1, __shfl_xor_sync(FULL, tm1, 1));
        tm1 = fmaxf(tm1, __shfl_xor_sync(FULL, tm1, 2));
        float mn0 = fmaxf(m0, tm0), mn1 = fmaxf(m1, tm1);
        float al0 = __expf(m0 - mn0), al1 = __expf(m1 - mn1);
        m0 = mn0; m1 = mn1;
        float ps0 = 0.f, ps1 = 0.f;
#pragma unroll
        for (int nt = 0; nt < 4; nt++) {
            float e0 = __expf(sc[nt][0] - mn0);
            float e1 = __expf(sc[nt][1] - mn0);
            float e2 = __expf(sc[nt][2] - mn1);
            float e3 = __expf(sc[nt][3] - mn1);
            ps0 += e0 + e1; ps1 += e2 + e3;
            sc[nt][0] = f2tf32(e0); sc[nt][1] = f2tf32(e1);
            sc[nt][2] = f2tf32(e2); sc[nt][3] = f2tf32(e3);
        }
        ps0 += __shfl_xor_sync(FULL, ps0, 1);
        ps0 += __shfl_xor_sync(FULL, ps0, 2);
        ps1 += __shfl_xor_sync(FULL, ps1, 1);
        ps1 += __shfl_xor_sync(FULL, ps1, 2);
        l0 = l0 * al0 + ps0;
        l1 = l1 * al1 + ps1;

#pragma unroll
        for (int nt = 0; nt < 8; nt++) {
            o[nt][0] *= al0; o[nt][1] *= al0;
            o[nt][2] *= al1; o[nt][3] *= al1;
        }

        // O += P V
#pragma unroll
        for (int ks = 0; ks < 4; ks++) {
            float t00 = __shfl_sync(FULL, sc[ks][0], src0);
            float t01 = __shfl_sync(FULL, sc[ks][1], src0);
            float t10 = __shfl_sync(FULL, sc[ks][2], src0);
            float t11 = __shfl_sync(FULL, sc[ks][3], src0);
            float u00 = __shfl_sync(FULL, sc[ks][0], src1);
            float u01 = __shfl_sync(FULL, sc[ks][1], src1);
            float u10 = __shfl_sync(FULL, sc[ks][2], src1);
            float u11 = __shfl_sync(FULL, sc[ks][3], src1);
            unsigned af[4];
            af[0] = __float_as_uint(odd ? t01 : t00);
            af[1] = __float_as_uint(odd ? t11 : t10);
            af[2] = __float_as_uint(odd ? u01 : u00);
            af[3] = __float_as_uint(odd ? u11 : u10);
#pragma unroll
            for (int nt = 0; nt < 8; nt++) {
                int d = nt * 8 + lr;
                unsigned bf[2];
                bf[0] = __float_as_uint(Vs[(ks * 8 + lc) * VP + d]);
                bf[1] = __float_as_uint(Vs[(ks * 8 + lc + 4) * VP + d]);
                mma_tf32(o[nt], af, bf);
            }
        }
    }
#undef ISSUE_KV

    // Finalize: tf32-rounded ctx
    {
        float li0 = 1.0f / l0, li1 = 1.0f / l1;
        int gq0 = q0 + r0, gq1 = q0 + r1;
#pragma unroll
        for (int nt = 0; nt < 8; nt++) {
            int d = h * DK + nt * 8 + 2 * lc;
            *(float2*)(g_ctx + (size_t)(b * SQ + gq0) * DMODEL + d) =
                make_float2(f2tf32(o[nt][0] * li0), f2tf32(o[nt][1] * li0));
            *(float2*)(g_ctx + (size_t)(b * SQ + gq1) * DMODEL + d) =
                make_float2(f2tf32(o[nt][2] * li1), f2tf32(o[nt][3] * li1));
        }
    }
}

// ---------------------------------------------------------------------------
extern "C" void kernel_launch(void* const* d_in, const int* in_sizes, int n_in,
                              void* d_out, int out_size) {
    (void)in_sizes; (void)n_in; (void)out_size;
    const float* hidden = (const float*)d_in[0];
    const float* mask   = (const float*)d_in[1];
    const float* Wqkv   = (const float*)d_in[2];
    const float* Wo     = (const float*)d_in[3];
    const float* emb    = (const float*)d_in[4];
    float* out = (float*)d_out;

    bias_kernel<<<16, 256>>>(emb);
    round_to<0><<<4096, 256>>>(hidden);   // -> g_hid
    round_to<1><<<3072, 256>>>(Wqkv);     // -> g_wqkv_r
    round_to<2><<<1024, 256>>>(Wo);       // -> g_wo_r

    const int gsm = (3 * (ASW + BSW)) * 4;  // 56832 B
    cudaFuncSetAttribute(gemm_tc<3072, 0>, cudaFuncAttributeMaxDynamicSharedMemorySize, gsm);
    cudaFuncSetAttribute(gemm_tc<1024, 1>, cudaFuncAttributeMaxDynamicSharedMemorySize, gsm);

    gemm_tc<3072, 0><<<dim3(24, 32), 256, gsm>>>(nullptr);

    const int asm_bytes = TOTW * 4;  // 71936 B
    cudaFuncSetAttribute(attn_tc, cudaFuncAttributeMaxDynamicSharedMemorySize,
                         asm_bytes);
    attn_tc<<<dim3(SQ / BQ, NH, BATCH), 256, asm_bytes>>>(mask);

    gemm_tc<1024, 1><<<dim3(8, 32), 256, gsm>>>(out);
}

// round 10
// speedup vs baseline: 2.3074x; 1.5757x over previous
#include <cuda_runtime.h>
#include <math.h>
#include <stdint.h>

#define BATCH 2
#define SQ 2048
#define NH 16
#define DK 64
#define DMODEL 1024
#define NREL 4095

__device__ float g_q[BATCH*NH*SQ*DK];
__device__ float g_k[BATCH*NH*SQ*DK];
__device__ float g_v[BATCH*NH*SQ*DK];
__device__ float g_ctx[(size_t)BATCH*SQ*DMODEL];
__device__ float g_bias[NH*NREL];

// ---------------------------------------------------------------------------
__device__ __forceinline__ float f2tf32(float x) {
    unsigned r;
    asm("cvt.rna.tf32.f32 %0, %1;" : "=r"(r) : "f"(x));
    return __uint_as_float(r);
}

__device__ __forceinline__ void mma_tf32(float c[4], const unsigned* a,
                                         const unsigned* b) {
    asm volatile(
        "mma.sync.aligned.m16n8k8.row.col.f32.tf32.tf32.f32 "
        "{%0,%1,%2,%3}, {%4,%5,%6,%7}, {%8,%9}, {%0,%1,%2,%3};\n"
        : "+f"(c[0]), "+f"(c[1]), "+f"(c[2]), "+f"(c[3])
        : "r"(a[0]), "r"(a[1]), "r"(a[2]), "r"(a[3]), "r"(b[0]), "r"(b[1]));
}

__device__ __forceinline__ uint32_t s2u(const void* p) {
    uint32_t a;
    asm("{ .reg .u64 t; cvta.to.shared.u64 t, %1; cvt.u32.u64 %0, t; }"
        : "=r"(a) : "l"(p));
    return a;
}
__device__ __forceinline__ void cpa16(uint32_t dst, const void* src) {
    asm volatile("cp.async.ca.shared.global [%0], [%1], 16;"
                 :: "r"(dst), "l"(src));
}
__device__ __forceinline__ void cpa4(uint32_t dst, const void* src) {
    asm volatile("cp.async.ca.shared.global [%0], [%1], 4;"
                 :: "r"(dst), "l"(src));
}
__device__ __forceinline__ void cpa_commit() {
    asm volatile("cp.async.commit_group;" ::: "memory");
}
template <int N>
__device__ __forceinline__ void cpa_wait() {
    asm volatile("cp.async.wait_group %0;" :: "n"(N) : "memory");
}

// ---------------------------------------------------------------------------
__global__ void bias_kernel(const float* __restrict__ emb) {
    int idx = blockIdx.x * blockDim.x + threadIdx.x;
    if (idx >= NREL) return;
    int rel = idx - (SQ - 1);
    int bucket = (rel > 0) ? 16 : 0;
    int rp = rel < 0 ? -rel : rel;
    int add;
    if (rp < 8) {
        add = rp;
    } else {
        float t = logf((float)rp * 0.125f);
        float u = t / 2.772588722239781f;
        float v = u * 8.0f;
        int w = 8 + (int)v;
        add = w < 15 ? w : 15;
    }
    bucket += add;
#pragma unroll
    for (int h = 0; h < NH; h++)
        g_bias[h * NREL + idx] = emb[bucket * NH + h];
}

// ---------------------------------------------------------------------------
// TF32 GEMM (identical to the 730us R3 version, except MODE 0 epilogue
// rounds q/k/v to tf32 so the attention kernel can cp.async them directly).
// ---------------------------------------------------------------------------
#define AP 20
#define BP 136

template <int NSZ, int MODE>
__global__ __launch_bounds__(256)
void gemm_tc(const float* __restrict__ A, const float* __restrict__ B,
             float* __restrict__ Cout) {
    __shared__ __align__(16) float As[2][128 * AP];
    __shared__ __align__(16) float Bs[2][16 * BP];

    const int n0 = blockIdx.x * 128;
    const int m0 = blockIdx.y * 128;
    const int tid = threadIdx.x;
    const int warp = tid >> 5, lane = tid & 31;
    const int wy = warp >> 2, wx = warp & 3;
    const int lr = lane >> 2, lc = lane & 3;

    const float* Abase = (MODE == 0) ? A : (const float*)g_ctx;
    const float* Ap = Abase + (size_t)m0 * 1024;
    const float* Bp = B + n0;

    const int fa = 2 * tid;
    const int a_row0 = fa >> 2,       a_c0 = (fa & 3) * 4;
    const int a_row1 = (fa + 1) >> 2, a_c1 = ((fa + 1) & 3) * 4;
    const int b_row0 = fa >> 5,       b_c0 = (fa & 31) * 4;
    const int b_row1 = (fa + 1) >> 5, b_c1 = ((fa + 1) & 31) * 4;

    float acc[4][4][4];
#pragma unroll
    for (int i = 0; i < 4; i++)
#pragma unroll
        for (int j = 0; j < 4; j++)
#pragma unroll
            for (int r = 0; r < 4; r++) acc[i][j][r] = 0.f;

    float4 pa0, pa1, pb0, pb1;
    pa0 = *(const float4*)(Ap + (size_t)a_row0 * 1024 + a_c0);
    pa1 = *(const float4*)(Ap + (size_t)a_row1 * 1024 + a_c1);
    pb0 = *(const float4*)(Bp + (size_t)b_row0 * NSZ + b_c0);
    pb1 = *(const float4*)(Bp + (size_t)b_row1 * NSZ + b_c1);

#define STORE_STAGE(st)                                   \
    do {                                                  \
        float* as = As[st]; float* bs = Bs[st];           \
        as[a_row0 * AP + a_c0 + 0] = f2tf32(pa0.x);       \
        as[a_row0 * AP + a_c0 + 1] = f2tf32(pa0.y);       \
        as[a_row0 * AP + a_c0 + 2] = f2tf32(pa0.z);       \
        as[a_row0 * AP + a_c0 + 3] = f2tf32(pa0.w);       \
        as[a_row1 * AP + a_c1 + 0] = f2tf32(pa1.x);       \
        as[a_row1 * AP + a_c1 + 1] = f2tf32(pa1.y);       \
        as[a_row1 * AP + a_c1 + 2] = f2tf32(pa1.z);       \
        as[a_row1 * AP + a_c1 + 3] = f2tf32(pa1.w);       \
        bs[b_row0 * BP + b_c0 + 0] = f2tf32(pb0.x);       \
        bs[b_row0 * BP + b_c0 + 1] = f2tf32(pb0.y);       \
        bs[b_row0 * BP + b_c0 + 2] = f2tf32(pb0.z);       \
        bs[b_row0 * BP + b_c0 + 3] = f2tf32(pb0.w);       \
        bs[b_row1 * BP + b_c1 + 0] = f2tf32(pb1.x);       \
        bs[b_row1 * BP + b_c1 + 1] = f2tf32(pb1.y);       \
        bs[b_row1 * BP + b_c1 + 2] = f2tf32(pb1.z);       \
        bs[b_row1 * BP + b_c1 + 3] = f2tf32(pb1.w);       \
    } while (0)

    STORE_STAGE(0);
    int s = 0;

    for (int k0 = 0; k0 < 1024; k0 += 16) {
        __syncthreads();
        const bool more = (k0 + 16 < 1024);
        if (more) {
            pa0 = *(const float4*)(Ap + (size_t)a_row0 * 1024 + k0 + 16 + a_c0);
            pa1 = *(const float4*)(Ap + (size_t)a_row1 * 1024 + k0 + 16 + a_c1);
            pb0 = *(const float4*)(Bp + (size_t)(k0 + 16 + b_row0) * NSZ + b_c0);
            pb1 = *(const float4*)(Bp + (size_t)(k0 + 16 + b_row1) * NSZ + b_c1);
        }
        const float* as = As[s];
        const float* bs = Bs[s];
#pragma unroll
        for (int ks = 0; ks < 2; ks++) {
            unsigned af[4][4], bf[4][2];
#pragma unroll
            for (int mt = 0; mt < 4; mt++) {
                int r0 = wy * 64 + mt * 16 + lr;
                af[mt][0] = __float_as_uint(as[r0 * AP + ks * 8 + lc]);
                af[mt][1] = __float_as_uint(as[(r0 + 8) * AP + ks * 8 + lc]);
                af[mt][2] = __float_as_uint(as[r0 * AP + ks * 8 + lc + 4]);
                af[mt][3] = __float_as_uint(as[(r0 + 8) * AP + ks * 8 + lc + 4]);
            }
#pragma unroll
            for (int nt = 0; nt < 4; nt++) {
                int n = wx * 32 + nt * 8 + lr;
                bf[nt][0] = __float_as_uint(bs[(ks * 8 + lc) * BP + n]);
                bf[nt][1] = __float_as_uint(bs[(ks * 8 + lc + 4) * BP + n]);
            }
#pragma unroll
            for (int mt = 0; mt < 4; mt++)
#pragma unroll
                for (int nt = 0; nt < 4; nt++)
                    mma_tf32(acc[mt][nt], af[mt], bf[nt]);
        }
        if (more) STORE_STAGE(s ^ 1);
        s ^= 1;
    }
#undef STORE_STAGE

#pragma unroll
    for (int mt = 0; mt < 4; mt++) {
        int gm0 = m0 + wy * 64 + mt * 16 + lr;
#pragma unroll
        for (int nt = 0; nt < 4; nt++) {
            int gn = n0 + wx * 32 + nt * 8 + 2 * lc;
            if (MODE == 1) {
                *(float2*)(Cout + (size_t)gm0 * NSZ + gn) =
                    make_float2(acc[mt][nt][0], acc[mt][nt][1]);
                *(float2*)(Cout + (size_t)(gm0 + 8) * NSZ + gn) =
                    make_float2(acc[mt][nt][2], acc[mt][nt][3]);
            } else {
                const int part = gn >> 10;
                const int h = (gn & 1023) >> 6;
                const int d = gn & 63;
                float* dst = (part == 0) ? g_q : (part == 1) ? g_k : g_v;
                {
                    int b = gm0 >> 11, sq = gm0 & 2047;
                    float* row = dst + ((size_t)((b * NH + h) * SQ) + sq) * DK;
                    *(float2*)(row + d) =
                        make_float2(f2tf32(acc[mt][nt][0]), f2tf32(acc[mt][nt][1]));
                }
                {
                    int gm1 = gm0 + 8;
                    int b = gm1 >> 11, sq = gm1 & 2047;
                    float* row = dst + ((size_t)((b * NH + h) * SQ) + sq) * DK;
                    *(float2*)(row + d) =
                        make_float2(f2tf32(acc[mt][nt][2]), f2tf32(acc[mt][nt][3]));
                }
            }
        }
    }
}

// ---------------------------------------------------------------------------
// Flash attention: BQ=128, BKV=64 (R3 compute), K/V/bias double-buffered
// via cp.async. q/k/v are pre-rounded to tf32 by the QKV GEMM epilogue.
// ---------------------------------------------------------------------------
#define BQ 128
#define BKV 64
#define QP 68
#define KP 68
#define VP 72
#define QW (BQ * QP)            // 8704
#define KW (BKV * KP)           // 4352 per stage
#define VW (BKV * VP)           // 4608 per stage
#define KOFF QW                 // 8704
#define VOFF (QW + 2 * KW)      // 17408
#define BOFF (VOFF + 2 * VW)    // 26624
#define TOTW (BOFF + 2 * 192)   // 27008 words = 108032 B

__global__ __launch_bounds__(256)
void attn_tc(const float* __restrict__ mask) {
    extern __shared__ __align__(16) float sm[];
    const uint32_t sb = s2u(sm);

    const int q0 = blockIdx.x * BQ;
    const int h  = blockIdx.y;
    const int b  = blockIdx.z;
    const int tid = threadIdx.x;
    const int warp = tid >> 5, lane = tid & 31;
    const int lr = lane >> 2, lc = lane & 3;
    const int r0 = warp * 16 + lr;
    const int r1 = r0 + 8;

    const float* Qg = g_q + ((size_t)(b * NH + h) * SQ + q0) * DK;
    const float* Kg = g_k + (size_t)(b * NH + h) * SQ * DK;
    const float* Vg = g_v + (size_t)(b * NH + h) * SQ * DK;
    const float* Mg = mask + (size_t)b * SQ * SQ;
    const float* Bg = g_bias + h * NREL;

    // K/V loader: each of 256 threads copies 16 floats of K and 16 of V.
    const int kvr = tid >> 2;           // row 0..63
    const int kvc = (tid & 3) * 16;     // col base 0,16,32,48

#define ISSUE_KV(st, t)                                                       \
    do {                                                                      \
        const float* ksrc = Kg + (size_t)((t) * BKV + kvr) * DK + kvc;        \
        uint32_t kdst = sb + (KOFF + (st) * KW + kvr * KP + kvc) * 4;         \
        cpa16(kdst,      ksrc);                                               \
        cpa16(kdst + 16, ksrc + 4);                                           \
        cpa16(kdst + 32, ksrc + 8);                                           \
        cpa16(kdst + 48, ksrc + 12);                                          \
        const float* vsrc = Vg + (size_t)((t) * BKV + kvr) * DK + kvc;        \
        uint32_t vdst = sb + (VOFF + (st) * VW + kvr * VP + kvc) * 4;         \
        cpa16(vdst,      vsrc);                                               \
        cpa16(vdst + 16, vsrc + 4);                                           \
        cpa16(vdst + 32, vsrc + 8);                                           \
        cpa16(vdst + 48, vsrc + 12);                                          \
        if (tid < 191)                                                        \
            cpa4(sb + (BOFF + (st) * 192 + tid) * 4,                          \
                 Bg + (t) * BKV - q0 + tid + 1920);                           \
    } while (0)

    // Prologue: Q + tile0 K/V/bias, one group.
#pragma unroll
    for (int t = 0; t < 8; t++) {
        int f = tid + t * 256;
        int r = f >> 4, c4 = (f & 15) * 4;
        cpa16(sb + (r * QP + c4) * 4, Qg + r * DK + c4);
    }
    ISSUE_KV(0, 0);
    cpa_commit();

    float m0 = -3.0e38f, m1 = -3.0e38f, l0 = 0.f, l1 = 0.f;
    float o[8][4];
#pragma unroll
    for (int nt = 0; nt < 8; nt++)
#pragma unroll
        for (int r = 0; r < 4; r++) o[nt][r] = 0.f;

    const unsigned FULL = 0xffffffffu;
    const int src0 = (lane & 28) | (lc >> 1);
    const int src1 = src0 + 2;
    const bool odd = (lc & 1) != 0;

    for (int it = 0; it < SQ / BKV; it++) {
        const int s = it & 1;
        cpa_wait<0>();
        __syncthreads();
        if (it + 1 < SQ / BKV) ISSUE_KV(s ^ 1, it + 1);
        cpa_commit();

        const float* Ks = sm + KOFF + s * KW;
        const float* Vs = sm + VOFF + s * VW;
        const float* Bs = sm + BOFF + s * 192;
        const int k0 = it * BKV;

        // S = Q K^T : 16x64 per warp
        float sc[8][4];
#pragma unroll
        for (int nt = 0; nt < 8; nt++)
#pragma unroll
            for (int r = 0; r < 4; r++) sc[nt][r] = 0.f;

#pragma unroll
        for (int ks = 0; ks < 8; ks++) {
            unsigned af[4], bf[8][2];
            af[0] = __float_as_uint(sm[r0 * QP + ks * 8 + lc]);
            af[1] = __float_as_uint(sm[r1 * QP + ks * 8 + lc]);
            af[2] = __float_as_uint(sm[r0 * QP + ks * 8 + lc + 4]);
            af[3] = __float_as_uint(sm[r1 * QP + ks * 8 + lc + 4]);
#pragma unroll
            for (int nt = 0; nt < 8; nt++) {
                int key = nt * 8 + lr;
                bf[nt][0] = __float_as_uint(Ks[key * KP + ks * 8 + lc]);
                bf[nt][1] = __float_as_uint(Ks[key * KP + ks * 8 + lc + 4]);
            }
#pragma unroll
            for (int nt = 0; nt < 8; nt++)
                mma_tf32(sc[nt], af, bf[nt]);
        }

        // scale + mask + bias
        {
            int gq0 = q0 + r0, gq1 = q0 + r1;
#pragma unroll
            for (int nt = 0; nt < 8; nt++) {
                int col = nt * 8 + 2 * lc;
                int kg = k0 + col;
                float2 mv0 = *(const float2*)(Mg + (size_t)gq0 * SQ + kg);
                float2 mv1 = *(const float2*)(Mg + (size_t)gq1 * SQ + kg);
                float b00 = Bs[col - r0 + 127];
                float b01 = Bs[col + 1 - r0 + 127];
                float b10 = Bs[col - r1 + 127];
                float b11 = Bs[col + 1 - r1 + 127];
                sc[nt][0] = sc[nt][0] * 0.125f * mv0.x + (b00 - 10000.f * (1.f - mv0.x));
                sc[nt][1] = sc[nt][1] * 0.125f * mv0.y + (b01 - 10000.f * (1.f - mv0.y));
                sc[nt][2] = sc[nt][2] * 0.125f * mv1.x + (b10 - 10000.f * (1.f - mv1.x));
                sc[nt][3] = sc[nt][3] * 0.125f * mv1.y + (b11 - 10000.f * (1.f - mv1.y));
            }
        }

        // Online softmax in registers
        float tm0 = -3.0e38f, tm1 = -3.0e38f;
#pragma unroll
        for (int nt = 0; nt < 8; nt++) {
            tm0 = fmaxf(tm0, fmaxf(sc[nt][0], sc[nt][1]));
            tm1 = fmaxf(tm1, fmaxf(sc[nt][2], sc[nt][3]));
        }
        tm0 = fmaxf(tm0, __shfl_xor_sync(FULL, tm0, 1));
        tm0 = fmaxf(tm0, __shfl_xor_sync(FULL, tm0, 2));
        tm1 = fmaxf(tm1, __shfl_xor_sync(FULL, tm1, 1));
        tm1 = fmaxf(tm1, __shfl_xor_sync(FULL, tm1, 2));
        float mn0 = fmaxf(m0, tm0), mn1 = fmaxf(m1, tm1);
        float al0 = __expf(m0 - mn0), al1 = __expf(m1 - mn1);
        m0 = mn0; m1 = mn1;
        float ps0 = 0.f, ps1 = 0.f;
#pragma unroll
        for (int nt = 0; nt < 8; nt++) {
            float e0 = __expf(sc[nt][0] - mn0);
            float e1 = __expf(sc[nt][1] - mn0);
            float e2 = __expf(sc[nt][2] - mn1);
            float e3 = __expf(sc[nt][3] - mn1);
            ps0 += e0 + e1; ps1 += e2 + e3;
            sc[nt][0] = f2tf32(e0); sc[nt][1] = f2tf32(e1);
            sc[nt][2] = f2tf32(e2); sc[nt][3] = f2tf32(e3);
        }
        ps0 += __shfl_xor_sync(FULL, ps0, 1);
        ps0 += __shfl_xor_sync(FULL, ps0, 2);
        ps1 += __shfl_xor_sync(FULL, ps1, 1);
        ps1 += __shfl_xor_sync(FULL, ps1, 2);
        l0 = l0 * al0 + ps0;
        l1 = l1 * al1 + ps1;

#pragma unroll
        for (int nt = 0; nt < 8; nt++) {
            o[nt][0] *= al0; o[nt][1] *= al0;
            o[nt][2] *= al1; o[nt][3] *= al1;
        }

        // O += P V (P C-frag -> A-frag via shuffles)
#pragma unroll
        for (int ks = 0; ks < 8; ks++) {
            float t00 = __shfl_sync(FULL, sc[ks][0], src0);
            float t01 = __shfl_sync(FULL, sc[ks][1], src0);
            float t10 = __shfl_sync(FULL, sc[ks][2], src0);
            float t11 = __shfl_sync(FULL, sc[ks][3], src0);
            float u00 = __shfl_sync(FULL, sc[ks][0], src1);
            float u01 = __shfl_sync(FULL, sc[ks][1], src1);
            float u10 = __shfl_sync(FULL, sc[ks][2], src1);
            float u11 = __shfl_sync(FULL, sc[ks][3], src1);
            unsigned af[4];
            af[0] = __float_as_uint(odd ? t01 : t00);
            af[1] = __float_as_uint(odd ? t11 : t10);
            af[2] = __float_as_uint(odd ? u01 : u00);
            af[3] = __float_as_uint(odd ? u11 : u10);
#pragma unroll
            for (int nt = 0; nt < 8; nt++) {
                int d = nt * 8 + lr;
                unsigned bf[2];
                bf[0] = __float_as_uint(Vs[(ks * 8 + lc) * VP + d]);
                bf[1] = __float_as_uint(Vs[(ks * 8 + lc + 4) * VP + d]);
                mma_tf32(o[nt], af, bf);
            }
        }
    }
#undef ISSUE_KV

    // Finalize: O / l -> g_ctx [b*S+q][h*64+d]
    {
        float li0 = 1.0f / l0, li1 = 1.0f / l1;
        int gq0 = q0 + r0, gq1 = q0 + r1;
#pragma unroll
        for (int nt = 0; nt < 8; nt++) {
            int d = h * DK + nt * 8 + 2 * lc;
            *(float2*)(g_ctx + (size_t)(b * SQ + gq0) * DMODEL + d) =
                make_float2(o[nt][0] * li0, o[nt][1] * li0);
            *(float2*)(g_ctx + (size_t)(b * SQ + gq1) * DMODEL + d) =
                make_float2(o[nt][2] * li1, o[nt][3] * li1);
        }
    }
}

// ---------------------------------------------------------------------------
extern "C" void kernel_launch(void* const* d_in, const int* in_sizes, int n_in,
                              void* d_out, int out_size) {
    (void)in_sizes; (void)n_in; (void)out_size;
    const float* hidden = (const float*)d_in[0];
    const float* mask   = (const float*)d_in[1];
    const float* Wqkv   = (const float*)d_in[2];
    const float* Wo     = (const float*)d_in[3];
    const float* emb    = (const float*)d_in[4];
    float* out = (float*)d_out;

    bias_kernel<<<16, 256>>>(emb);

    gemm_tc<3072, 0><<<dim3(24, 32), 256>>>(hidden, Wqkv, nullptr);

    const int asm_bytes = TOTW * 4;  // 108032 B
    cudaFuncSetAttribute(attn_tc, cudaFuncAttributeMaxDynamicSharedMemorySize,
                         asm_bytes);
    attn_tc<<<dim3(SQ / BQ, NH, BATCH), 256, asm_bytes>>>(mask);

    gemm_tc<1024, 1><<<dim3(8, 32), 256>>>(nullptr, Wo, out);
}

// round 11
// speedup vs baseline: 2.3852x; 1.0337x over previous
#include <cuda_runtime.h>
#include <math.h>
#include <stdint.h>

#define BATCH 2
#define SQ 2048
#define NH 16
#define DK 64
#define DMODEL 1024
#define NREL 4095

__device__ float g_q[BATCH*NH*SQ*DK];
__device__ float g_k[BATCH*NH*SQ*DK];
__device__ float g_v[BATCH*NH*SQ*DK];
__device__ float g_ctx[(size_t)BATCH*SQ*DMODEL];
__device__ float g_bias[NH*NREL];
__device__ float g_hid[(size_t)BATCH*SQ*DMODEL];
__device__ float g_wqkv_r[DMODEL*3*DMODEL];
__device__ float g_wo_r[DMODEL*DMODEL];

// ---------------------------------------------------------------------------
__device__ __forceinline__ float f2tf32(float x) {
    unsigned r;
    asm("cvt.rna.tf32.f32 %0, %1;" : "=r"(r) : "f"(x));
    return __uint_as_float(r);
}

__device__ __forceinline__ void mma_tf32(float c[4], const unsigned* a,
                                         const unsigned* b) {
    asm volatile(
        "mma.sync.aligned.m16n8k8.row.col.f32.tf32.tf32.f32 "
        "{%0,%1,%2,%3}, {%4,%5,%6,%7}, {%8,%9}, {%0,%1,%2,%3};\n"
        : "+f"(c[0]), "+f"(c[1]), "+f"(c[2]), "+f"(c[3])
        : "r"(a[0]), "r"(a[1]), "r"(a[2]), "r"(a[3]), "r"(b[0]), "r"(b[1]));
}

__device__ __forceinline__ uint32_t s2u(const void* p) {
    uint32_t a;
    asm("{ .reg .u64 t; cvta.to.shared.u64 t, %1; cvt.u32.u64 %0, t; }"
        : "=r"(a) : "l"(p));
    return a;
}
__device__ __forceinline__ void cpa16(uint32_t dst, const void* src) {
    asm volatile("cp.async.ca.shared.global [%0], [%1], 16;"
                 :: "r"(dst), "l"(src));
}
__device__ __forceinline__ void cpa_commit() {
    asm volatile("cp.async.commit_group;" ::: "memory");
}
template <int N>
__device__ __forceinline__ void cpa_wait() {
    asm volatile("cp.async.wait_group %0;" :: "n"(N) : "memory");
}

// ---------------------------------------------------------------------------
__global__ void bias_kernel(const float* __restrict__ emb) {
    int idx = blockIdx.x * blockDim.x + threadIdx.x;
    if (idx >= NREL) return;
    int rel = idx - (SQ - 1);
    int bucket = (rel > 0) ? 16 : 0;
    int rp = rel < 0 ? -rel : rel;
    int add;
    if (rp < 8) {
        add = rp;
    } else {
        float t = logf((float)rp * 0.125f);
        float u = t / 2.772588722239781f;
        float v = u * 8.0f;
        int w = 8 + (int)v;
        add = w < 15 ? w : 15;
    }
    bucket += add;
#pragma unroll
    for (int h = 0; h < NH; h++)
        g_bias[h * NREL + idx] = emb[bucket * NH + h];
}

// Round input to tf32, destination global selected in DEVICE code.
template <int WHICH>
__global__ void round_to(const float* __restrict__ src) {
    float* dst = (WHICH == 0) ? g_hid : (WHICH == 1) ? g_wqkv_r : g_wo_r;
    size_t idx = (size_t)blockIdx.x * blockDim.x + threadIdx.x;
    float4 v = *(const float4*)(src + idx * 4);
    v.x = f2tf32(v.x); v.y = f2tf32(v.y); v.z = f2tf32(v.z); v.w = f2tf32(v.w);
    *(float4*)(dst + idx * 4) = v;
}

// ---------------------------------------------------------------------------
// TF32 GEMM: 3-stage cp.async, BK=32, CTA 128x128, 256 thr, warp tile 64x32.
// Inputs pre-rounded to tf32 (g_hid/g_wqkv_r/g_wo_r; g_ctx rounded by attn).
// ---------------------------------------------------------------------------
#define AP 36
#define BP 136
#define ASW (128 * AP)   // 4608 words / stage
#define BSW (32 * BP)    // 4352 words / stage

template <int NSZ, int MODE>
__global__ __launch_bounds__(256)
void gemm_tc(float* __restrict__ Cout) {
    extern __shared__ __align__(16) float smf[];
    const uint32_t sb = s2u(smf);

    const int n0 = blockIdx.x * 128;
    const int m0 = blockIdx.y * 128;
    const int tid = threadIdx.x;
    const int warp = tid >> 5, lane = tid & 31;
    const int wy = warp >> 2, wx = warp & 3;
    const int lr = lane >> 2, lc = lane & 3;

    const float* Ap = ((MODE == 0) ? g_hid : (const float*)g_ctx) + (size_t)m0 * 1024;
    const float* Bp = ((MODE == 0) ? g_wqkv_r : g_wo_r) + n0;

    // Loaders: A 128x32 (4 chunks/thread), B 32x128 (4 chunks/thread)
    const int arow = tid >> 1,  acol = (tid & 1) * 16;
    const int brow = tid >> 3,  bcol = (tid & 7) * 16;
    const uint32_t adst = sb + (arow * AP + acol) * 4;
    const uint32_t bdst = sb + (3 * ASW + brow * BP + bcol) * 4;

    float acc[4][4][4];
#pragma unroll
    for (int i = 0; i < 4; i++)
#pragma unroll
        for (int j = 0; j < 4; j++)
#pragma unroll
            for (int r = 0; r < 4; r++) acc[i][j][r] = 0.f;

#define ISSUE(st, k0)                                                         \
    do {                                                                      \
        const float* asrc = Ap + (size_t)arow * 1024 + (k0) + acol;           \
        uint32_t ad = adst + (st) * ASW * 4;                                  \
        cpa16(ad,      asrc);                                                 \
        cpa16(ad + 16, asrc + 4);                                             \
        cpa16(ad + 32, asrc + 8);                                             \
        cpa16(ad + 48, asrc + 12);                                            \
        const float* bsrc = Bp + (size_t)((k0) + brow) * NSZ + bcol;          \
        uint32_t bd = bdst + (st) * BSW * 4;                                  \
        cpa16(bd,      bsrc);                                                 \
        cpa16(bd + 16, bsrc + 4);                                             \
        cpa16(bd + 32, bsrc + 8);                                             \
        cpa16(bd + 48, bsrc + 12);                                            \
    } while (0)

    ISSUE(0, 0); cpa_commit();
    ISSUE(1, 32); cpa_commit();

    int s = 0;
    for (int it = 0; it < 32; it++) {
        cpa_wait<1>();
        __syncthreads();
        if (it + 2 < 32) ISSUE((it + 2) % 3, (it + 2) * 32);
        cpa_commit();

        const float* as = smf + s * ASW;
        const float* bs = smf + 3 * ASW + s * BSW;
#pragma unroll
        for (int ks = 0; ks < 4; ks++) {
            unsigned af[4][4], bf[4][2];
#pragma unroll
            for (int mt = 0; mt < 4; mt++) {
                int r0 = wy * 64 + mt * 16 + lr;
                af[mt][0] = __float_as_uint(as[r0 * AP + ks * 8 + lc]);
                af[mt][1] = __float_as_uint(as[(r0 + 8) * AP + ks * 8 + lc]);
                af[mt][2] = __float_as_uint(as[r0 * AP + ks * 8 + lc + 4]);
                af[mt][3] = __float_as_uint(as[(r0 + 8) * AP + ks * 8 + lc + 4]);
            }
#pragma unroll
            for (int nt = 0; nt < 4; nt++) {
                int n = wx * 32 + nt * 8 + lr;
                bf[nt][0] = __float_as_uint(bs[(ks * 8 + lc) * BP + n]);
                bf[nt][1] = __float_as_uint(bs[(ks * 8 + lc + 4) * BP + n]);
            }
#pragma unroll
            for (int mt = 0; mt < 4; mt++)
#pragma unroll
                for (int nt = 0; nt < 4; nt++)
                    mma_tf32(acc[mt][nt], af[mt], bf[nt]);
        }
        s = (s + 1) % 3;
    }
#undef ISSUE

#pragma unroll
    for (int mt = 0; mt < 4; mt++) {
        int gm0 = m0 + wy * 64 + mt * 16 + lr;
#pragma unroll
        for (int nt = 0; nt < 4; nt++) {
            int gn = n0 + wx * 32 + nt * 8 + 2 * lc;
            if (MODE == 1) {
                *(float2*)(Cout + (size_t)gm0 * NSZ + gn) =
                    make_float2(acc[mt][nt][0], acc[mt][nt][1]);
                *(float2*)(Cout + (size_t)(gm0 + 8) * NSZ + gn) =
                    make_float2(acc[mt][nt][2], acc[mt][nt][3]);
            } else {
                const int part = gn >> 10;
                const int h = (gn & 1023) >> 6;
                const int d = gn & 63;
                float* dst = (part == 0) ? g_q : (part == 1) ? g_k : g_v;
                {
                    int b = gm0 >> 11, sq = gm0 & 2047;
                    float* row = dst + ((size_t)((b * NH + h) * SQ) + sq) * DK;
                    *(float2*)(row + d) = make_float2(acc[mt][nt][0], acc[mt][nt][1]);
                }
                {
                    int gm1 = gm0 + 8;
                    int b = gm1 >> 11, sq = gm1 & 2047;
                    float* row = dst + ((size_t)((b * NH + h) * SQ) + sq) * DK;
                    *(float2*)(row + d) = make_float2(acc[mt][nt][2], acc[mt][nt][3]);
                }
            }
        }
    }
}

// ---------------------------------------------------------------------------
// Flash attention — exact R3 (730us) version; finalize rounds ctx to tf32
// so the MODE 1 GEMM can consume it without a cvt.
// ---------------------------------------------------------------------------
#define BQ 128
#define BKV 64
#define QP 68
#define KP 68
#define VP 72

__global__ __launch_bounds__(256)
void attn_tc(const float* __restrict__ mask) {
    extern __shared__ float sm[];
    float* Qs  = sm;
    float* Ks  = Qs + BQ * QP;
    float* Vs  = Ks + BKV * KP;
    float* Bsm = Vs + BKV * VP;

    const int q0 = blockIdx.x * BQ;
    const int h  = blockIdx.y;
    const int b  = blockIdx.z;
    const int tid = threadIdx.x;
    const int warp = tid >> 5, lane = tid & 31;
    const int lr = lane >> 2, lc = lane & 3;
    const int r0 = warp * 16 + lr;
    const int r1 = r0 + 8;

    const float* Qg = g_q + ((size_t)(b * NH + h) * SQ + q0) * DK;
    const float* Kg = g_k + (size_t)(b * NH + h) * SQ * DK;
    const float* Vg = g_v + (size_t)(b * NH + h) * SQ * DK;
    const float* Mg = mask + (size_t)b * SQ * SQ;
    const float* Bg = g_bias + h * NREL;

#pragma unroll
    for (int t = 0; t < 8; t++) {
        int f = tid + t * 256;
        int r = f >> 4, c4 = (f & 15) * 4;
        float4 v = *(const float4*)(Qg + r * DK + c4);
        Qs[r * QP + c4 + 0] = f2tf32(v.x);
        Qs[r * QP + c4 + 1] = f2tf32(v.y);
        Qs[r * QP + c4 + 2] = f2tf32(v.z);
        Qs[r * QP + c4 + 3] = f2tf32(v.w);
    }

    float m0 = -3.0e38f, m1 = -3.0e38f, l0 = 0.f, l1 = 0.f;
    float o[8][4];
#pragma unroll
    for (int nt = 0; nt < 8; nt++)
#pragma unroll
        for (int r = 0; r < 4; r++) o[nt][r] = 0.f;

    const unsigned FULL = 0xffffffffu;
    const int src0 = (lane & 28) | (lc >> 1);
    const int src1 = src0 + 2;
    const bool odd = (lc & 1) != 0;

    for (int k0 = 0; k0 < SQ; k0 += BKV) {
        __syncthreads();
#pragma unroll
        for (int t = 0; t < 4; t++) {
            int f = tid + t * 256;
            int r = f >> 4, c4 = (f & 15) * 4;
            float4 kv = *(const float4*)(Kg + (size_t)(k0 + r) * DK + c4);
            Ks[r * KP + c4 + 0] = f2tf32(kv.x);
            Ks[r * KP + c4 + 1] = f2tf32(kv.y);
            Ks[r * KP + c4 + 2] = f2tf32(kv.z);
            Ks[r * KP + c4 + 3] = f2tf32(kv.w);
            float4 vv = *(const float4*)(Vg + (size_t)(k0 + r) * DK + c4);
            Vs[r * VP + c4 + 0] = f2tf32(vv.x);
            Vs[r * VP + c4 + 1] = f2tf32(vv.y);
            Vs[r * VP + c4 + 2] = f2tf32(vv.z);
            Vs[r * VP + c4 + 3] = f2tf32(vv.w);
        }
        if (tid < 191)
            Bsm[tid] = Bg[k0 - q0 + tid - 127 + (SQ - 1)];
        __syncthreads();

        float sc[8][4];
#pragma unroll
        for (int nt = 0; nt < 8; nt++)
#pragma unroll
            for (int r = 0; r < 4; r++) sc[nt][r] = 0.f;

#pragma unroll
        for (int ks = 0; ks < 8; ks++) {
            unsigned af[4], bf[8][2];
            af[0] = __float_as_uint(Qs[r0 * QP + ks * 8 + lc]);
            af[1] = __float_as_uint(Qs[r1 * QP + ks * 8 + lc]);
            af[2] = __float_as_uint(Qs[r0 * QP + ks * 8 + lc + 4]);
            af[3] = __float_as_uint(Qs[r1 * QP + ks * 8 + lc + 4]);
#pragma unroll
            for (int nt = 0; nt < 8; nt++) {
                int key = nt * 8 + lr;
                bf[nt][0] = __float_as_uint(Ks[key * KP + ks * 8 + lc]);
                bf[nt][1] = __float_as_uint(Ks[key * KP + ks * 8 + lc + 4]);
            }
#pragma unroll
            for (int nt = 0; nt < 8; nt++)
                mma_tf32(sc[nt], af, bf[nt]);
        }

        {
            int gq0 = q0 + r0, gq1 = q0 + r1;
#pragma unroll
            for (int nt = 0; nt < 8; nt++) {
                int col = nt * 8 + 2 * lc;
                int kg = k0 + col;
                float2 mv0 = *(const float2*)(Mg + (size_t)gq0 * SQ + kg);
                float2 mv1 = *(const float2*)(Mg + (size_t)gq1 * SQ + kg);
                float b00 = Bsm[col - r0 + 127];
                float b01 = Bsm[col + 1 - r0 + 127];
                float b10 = Bsm[col - r1 + 127];
                float b11 = Bsm[col + 1 - r1 + 127];
                sc[nt][0] = sc[nt][0] * 0.125f * mv0.x + (b00 - 10000.f * (1.f - mv0.x));
                sc[nt][1] = sc[nt][1] * 0.125f * mv0.y + (b01 - 10000.f * (1.f - mv0.y));
                sc[nt][2] = sc[nt][2] * 0.125f * mv1.x + (b10 - 10000.f * (1.f - mv1.x));
                sc[nt][3] = sc[nt][3] * 0.125f * mv1.y + (b11 - 10000.f * (1.f - mv1.y));
            }
        }

        float tm0 = -3.0e38f, tm1 = -3.0e38f;
#pragma unroll
        for (int nt = 0; nt < 8; nt++) {
            tm0 = fmaxf(tm0, fmaxf(sc[nt][0], sc[nt][1]));
            tm1 = fmaxf(tm1, fmaxf(sc[nt][2], sc[nt][3]));
        }
        tm0 = fmaxf(tm0, __shfl_xor_sync(FULL, tm0, 1));
        tm0 = fmaxf(tm0, __shfl_xor_sync(FULL, tm0, 2));
        tm1 = fmaxf(tm1, __shfl_xor_sync(FULL, tm1, 1));
        tm1 = fmaxf(tm1, __shfl_xor_sync(FULL, tm1, 2));
        float mn0 = fmaxf(m0, tm0), mn1 = fmaxf(m1, tm1);
        float al0 = __expf(m0 - mn0), al1 = __expf(m1 - mn1);
        m0 = mn0; m1 = mn1;
        float ps0 = 0.f, ps1 = 0.f;
#pragma unroll
        for (int nt = 0; nt < 8; nt++) {
            float e0 = __expf(sc[nt][0] - mn0);
            float e1 = __expf(sc[nt][1] - mn0);
            float e2 = __expf(sc[nt][2] - mn1);
            float e3 = __expf(sc[nt][3] - mn1);
            ps0 += e0 + e1; ps1 += e2 + e3;
            sc[nt][0] = f2tf32(e0); sc[nt][1] = f2tf32(e1);
            sc[nt][2] = f2tf32(e2); sc[nt][3] = f2tf32(e3);
        }
        ps0 += __shfl_xor_sync(FULL, ps0, 1);
        ps0 += __shfl_xor_sync(FULL, ps0, 2);
        ps1 += __shfl_xor_sync(FULL, ps1, 1);
        ps1 += __shfl_xor_sync(FULL, ps1, 2);
        l0 = l0 * al0 + ps0;
        l1 = l1 * al1 + ps1;

#pragma unroll
        for (int nt = 0; nt < 8; nt++) {
            o[nt][0] *= al0; o[nt][1] *= al0;
            o[nt][2] *= al1; o[nt][3] *= al1;
        }

#pragma unroll
        for (int ks = 0; ks < 8; ks++) {
            float t00 = __shfl_sync(FULL, sc[ks][0], src0);
            float t01 = __shfl_sync(FULL, sc[ks][1], src0);
            float t10 = __shfl_sync(FULL, sc[ks][2], src0);
            float t11 = __shfl_sync(FULL, sc[ks][3], src0);
            float u00 = __shfl_sync(FULL, sc[ks][0], src1);
            float u01 = __shfl_sync(FULL, sc[ks][1], src1);
            float u10 = __shfl_sync(FULL, sc[ks][2], src1);
            float u11 = __shfl_sync(FULL, sc[ks][3], src1);
            unsigned af[4];
            af[0] = __float_as_uint(odd ? t01 : t00);
            af[1] = __float_as_uint(odd ? t11 : t10);
            af[2] = __float_as_uint(odd ? u01 : u00);
            af[3] = __float_as_uint(odd ? u11 : u10);
#pragma unroll
            for (int nt = 0; nt < 8; nt++) {
                int d = nt * 8 + lr;
                unsigned bf[2];
                bf[0] = __float_as_uint(Vs[(ks * 8 + lc) * VP + d]);
                bf[1] = __float_as_uint(Vs[(ks * 8 + lc + 4) * VP + d]);
                mma_tf32(o[nt], af, bf);
            }
        }
    }

    // Finalize: tf32-rounded ctx (consumed raw by cp.async MODE 1 GEMM)
    {
        float li0 = 1.0f / l0, li1 = 1.0f / l1;
        int gq0 = q0 + r0, gq1 = q0 + r1;
#pragma unroll
        for (int nt = 0; nt < 8; nt++) {
            int d = h * DK + nt * 8 + 2 * lc;
            *(float2*)(g_ctx + (size_t)(b * SQ + gq0) * DMODEL + d) =
                make_float2(f2tf32(o[nt][0] * li0), f2tf32(o[nt][1] * li0));
            *(float2*)(g_ctx + (size_t)(b * SQ + gq1) * DMODEL + d) =
                make_float2(f2tf32(o[nt][2] * li1), f2tf32(o[nt][3] * li1));
        }
    }
}

// ---------------------------------------------------------------------------
extern "C" void kernel_launch(void* const* d_in, const int* in_sizes, int n_in,
                              void* d_out, int out_size) {
    (void)in_sizes; (void)n_in; (void)out_size;
    const float* hidden = (const float*)d_in[0];
    const float* mask   = (const float*)d_in[1];
    const float* Wqkv   = (const float*)d_in[2];
    const float* Wo     = (const float*)d_in[3];
    const float* emb    = (const float*)d_in[4];
    float* out = (float*)d_out;

    bias_kernel<<<16, 256>>>(emb);
    round_to<0><<<4096, 256>>>(hidden);   // -> g_hid
    round_to<1><<<3072, 256>>>(Wqkv);     // -> g_wqkv_r
    round_to<2><<<1024, 256>>>(Wo);       // -> g_wo_r

    const int gsm = 3 * (ASW + BSW) * 4;  // 107520 B
    cudaFuncSetAttribute(gemm_tc<3072, 0>, cudaFuncAttributeMaxDynamicSharedMemorySize, gsm);
    cudaFuncSetAttribute(gemm_tc<1024, 1>, cudaFuncAttributeMaxDynamicSharedMemorySize, gsm);

    gemm_tc<3072, 0><<<dim3(24, 32), 256, gsm>>>(nullptr);

    const int smem_bytes = (BQ * QP + BKV * KP + BKV * VP + 192) * 4;
    cudaFuncSetAttribute(attn_tc, cudaFuncAttributeMaxDynamicSharedMemorySize,
                         smem_bytes);
    attn_tc<<<dim3(SQ / BQ, NH, BATCH), 256, smem_bytes>>>(mask);

    gemm_tc<1024, 1><<<dim3(8, 32), 256, gsm>>>(out);
}

// round 12
// speedup vs baseline: 2.6107x; 1.0945x over previous
#include <cuda_runtime.h>
#include <math.h>
#include <stdint.h>

#define BATCH 2
#define SQ 2048
#define NH 16
#define DK 64
#define DMODEL 1024
#define NREL 4095

__device__ float g_q[BATCH*NH*SQ*DK];
__device__ float g_k[BATCH*NH*SQ*DK];
__device__ float g_v[BATCH*NH*SQ*DK];
__device__ float g_ctx[(size_t)BATCH*SQ*DMODEL];
__device__ float g_bias[NH*NREL];

// ---------------------------------------------------------------------------
__device__ __forceinline__ float f2tf32(float x) {
    unsigned r;
    asm("cvt.rna.tf32.f32 %0, %1;" : "=r"(r) : "f"(x));
    return __uint_as_float(r);
}

__device__ __forceinline__ void mma_tf32(float c[4], const unsigned* a,
                                         const unsigned* b) {
    asm volatile(
        "mma.sync.aligned.m16n8k8.row.col.f32.tf32.tf32.f32 "
        "{%0,%1,%2,%3}, {%4,%5,%6,%7}, {%8,%9}, {%0,%1,%2,%3};\n"
        : "+f"(c[0]), "+f"(c[1]), "+f"(c[2]), "+f"(c[3])
        : "r"(a[0]), "r"(a[1]), "r"(a[2]), "r"(a[3]), "r"(b[0]), "r"(b[1]));
}

__device__ __forceinline__ uint32_t s2u(const void* p) {
    uint32_t a;
    asm("{ .reg .u64 t; cvta.to.shared.u64 t, %1; cvt.u32.u64 %0, t; }"
        : "=r"(a) : "l"(p));
    return a;
}

// ldmatrix x4 on 32-bit data: each 8x8 b16 matrix = 8x4 f32 tile; result
// thread t holds f32 at (row t>>2, col t&3) of its matrix.
__device__ __forceinline__ void ldsm4(unsigned* r, uint32_t addr) {
    asm volatile(
        "ldmatrix.sync.aligned.m8n8.x4.shared.b16 {%0,%1,%2,%3}, [%4];"
        : "=r"(r[0]), "=r"(r[1]), "=r"(r[2]), "=r"(r[3]) : "r"(addr));
}

// ---------------------------------------------------------------------------
__global__ void bias_kernel(const float* __restrict__ emb) {
    int idx = blockIdx.x * blockDim.x + threadIdx.x;
    if (idx >= NREL) return;
    int rel = idx - (SQ - 1);
    int bucket = (rel > 0) ? 16 : 0;
    int rp = rel < 0 ? -rel : rel;
    int add;
    if (rp < 8) {
        add = rp;
    } else {
        float t = logf((float)rp * 0.125f);
        float u = t / 2.772588722239781f;
        float v = u * 8.0f;
        int w = 8 + (int)v;
        add = w < 15 ? w : 15;
    }
    bucket += add;
#pragma unroll
    for (int h = 0; h < NH; h++)
        g_bias[h * NREL + idx] = emb[bucket * NH + h];
}

// ---------------------------------------------------------------------------
// TF32 GEMM (R3 body); A-fragments now via ldmatrix.x4.
// ---------------------------------------------------------------------------
#define AP 20
#define BP 136

template <int NSZ, int MODE>
__global__ __launch_bounds__(256)
void gemm_tc(const float* __restrict__ A, const float* __restrict__ B,
             float* __restrict__ Cout) {
    __shared__ __align__(16) float As[2][128 * AP];
    __shared__ __align__(16) float Bs[2][16 * BP];

    const int n0 = blockIdx.x * 128;
    const int m0 = blockIdx.y * 128;
    const int tid = threadIdx.x;
    const int warp = tid >> 5, lane = tid & 31;
    const int wy = warp >> 2, wx = warp & 3;
    const int lr = lane >> 2, lc = lane & 3;

    // ldmatrix lane geometry for A-fragments
    const int a_lrow = (lane & 7) + ((lane >> 3) & 1) * 8;
    const int a_lcol = ((lane >> 4) & 1) * 4;
    const uint32_t sbA0 = s2u(As[0]);
    const uint32_t sbA1 = s2u(As[1]);

    const float* Abase = (MODE == 0) ? A : (const float*)g_ctx;
    const float* Ap = Abase + (size_t)m0 * 1024;
    const float* Bp = B + n0;

    const int fa = 2 * tid;
    const int a_row0 = fa >> 2,       a_c0 = (fa & 3) * 4;
    const int a_row1 = (fa + 1) >> 2, a_c1 = ((fa + 1) & 3) * 4;
    const int b_row0 = fa >> 5,       b_c0 = (fa & 31) * 4;
    const int b_row1 = (fa + 1) >> 5, b_c1 = ((fa + 1) & 31) * 4;

    float acc[4][4][4];
#pragma unroll
    for (int i = 0; i < 4; i++)
#pragma unroll
        for (int j = 0; j < 4; j++)
#pragma unroll
            for (int r = 0; r < 4; r++) acc[i][j][r] = 0.f;

    float4 pa0, pa1, pb0, pb1;
    pa0 = *(const float4*)(Ap + (size_t)a_row0 * 1024 + a_c0);
    pa1 = *(const float4*)(Ap + (size_t)a_row1 * 1024 + a_c1);
    pb0 = *(const float4*)(Bp + (size_t)b_row0 * NSZ + b_c0);
    pb1 = *(const float4*)(Bp + (size_t)b_row1 * NSZ + b_c1);

#define STORE_STAGE(st)                                   \
    do {                                                  \
        float* as = As[st]; float* bs = Bs[st];           \
        as[a_row0 * AP + a_c0 + 0] = f2tf32(pa0.x);       \
        as[a_row0 * AP + a_c0 + 1] = f2tf32(pa0.y);       \
        as[a_row0 * AP + a_c0 + 2] = f2tf32(pa0.z);       \
        as[a_row0 * AP + a_c0 + 3] = f2tf32(pa0.w);       \
        as[a_row1 * AP + a_c1 + 0] = f2tf32(pa1.x);       \
        as[a_row1 * AP + a_c1 + 1] = f2tf32(pa1.y);       \
        as[a_row1 * AP + a_c1 + 2] = f2tf32(pa1.z);       \
        as[a_row1 * AP + a_c1 + 3] = f2tf32(pa1.w);       \
        bs[b_row0 * BP + b_c0 + 0] = f2tf32(pb0.x);       \
        bs[b_row0 * BP + b_c0 + 1] = f2tf32(pb0.y);       \
        bs[b_row0 * BP + b_c0 + 2] = f2tf32(pb0.z);       \
        bs[b_row0 * BP + b_c0 + 3] = f2tf32(pb0.w);       \
        bs[b_row1 * BP + b_c1 + 0] = f2tf32(pb1.x);       \
        bs[b_row1 * BP + b_c1 + 1] = f2tf32(pb1.y);       \
        bs[b_row1 * BP + b_c1 + 2] = f2tf32(pb1.z);       \
        bs[b_row1 * BP + b_c1 + 3] = f2tf32(pb1.w);       \
    } while (0)

    STORE_STAGE(0);
    int s = 0;

    for (int k0 = 0; k0 < 1024; k0 += 16) {
        __syncthreads();
        const bool more = (k0 + 16 < 1024);
        if (more) {
            pa0 = *(const float4*)(Ap + (size_t)a_row0 * 1024 + k0 + 16 + a_c0);
            pa1 = *(const float4*)(Ap + (size_t)a_row1 * 1024 + k0 + 16 + a_c1);
            pb0 = *(const float4*)(Bp + (size_t)(k0 + 16 + b_row0) * NSZ + b_c0);
            pb1 = *(const float4*)(Bp + (size_t)(k0 + 16 + b_row1) * NSZ + b_c1);
        }
        const uint32_t asb = s ? sbA1 : sbA0;
        const float* bs = Bs[s];
#pragma unroll
        for (int ks = 0; ks < 2; ks++) {
            unsigned af[4][4], bf[4][2];
#pragma unroll
            for (int mt = 0; mt < 4; mt++)
                ldsm4(af[mt], asb + (uint32_t)((wy * 64 + mt * 16 + a_lrow) * AP
                                              + ks * 8 + a_lcol) * 4u);
#pragma unroll
            for (int nt = 0; nt < 4; nt++) {
                int n = wx * 32 + nt * 8 + lr;
                bf[nt][0] = __float_as_uint(bs[(ks * 8 + lc) * BP + n]);
                bf[nt][1] = __float_as_uint(bs[(ks * 8 + lc + 4) * BP + n]);
            }
#pragma unroll
            for (int mt = 0; mt < 4; mt++)
#pragma unroll
                for (int nt = 0; nt < 4; nt++)
                    mma_tf32(acc[mt][nt], af[mt], bf[nt]);
        }
        if (more) STORE_STAGE(s ^ 1);
        s ^= 1;
    }
#undef STORE_STAGE

#pragma unroll
    for (int mt = 0; mt < 4; mt++) {
        int gm0 = m0 + wy * 64 + mt * 16 + lr;
#pragma unroll
        for (int nt = 0; nt < 4; nt++) {
            int gn = n0 + wx * 32 + nt * 8 + 2 * lc;
            if (MODE == 1) {
                *(float2*)(Cout + (size_t)gm0 * NSZ + gn) =
                    make_float2(acc[mt][nt][0], acc[mt][nt][1]);
                *(float2*)(Cout + (size_t)(gm0 + 8) * NSZ + gn) =
                    make_float2(acc[mt][nt][2], acc[mt][nt][3]);
            } else {
                const int part = gn >> 10;
                const int h = (gn & 1023) >> 6;
                const int d = gn & 63;
                float* dst = (part == 0) ? g_q : (part == 1) ? g_k : g_v;
                {
                    int b = gm0 >> 11, sq = gm0 & 2047;
                    float* row = dst + ((size_t)((b * NH + h) * SQ) + sq) * DK;
                    *(float2*)(row + d) = make_float2(acc[mt][nt][0], acc[mt][nt][1]);
                }
                {
                    int gm1 = gm0 + 8;
                    int b = gm1 >> 11, sq = gm1 & 2047;
                    float* row = dst + ((size_t)((b * NH + h) * SQ) + sq) * DK;
                    *(float2*)(row + d) = make_float2(acc[mt][nt][2], acc[mt][nt][3]);
                }
            }
        }
    }
}

// ---------------------------------------------------------------------------
// Flash attention (R3 body); Q and K fragments now via ldmatrix.x4.
// ---------------------------------------------------------------------------
#define BQ 128
#define BKV 64
#define QP 68
#define KP 68
#define VP 72

__global__ __launch_bounds__(256)
void attn_tc(const float* __restrict__ mask) {
    extern __shared__ float sm[];
    float* Qs  = sm;
    float* Ks  = Qs + BQ * QP;
    float* Vs  = Ks + BKV * KP;
    float* Bsm = Vs + BKV * VP;

    const int q0 = blockIdx.x * BQ;
    const int h  = blockIdx.y;
    const int b  = blockIdx.z;
    const int tid = threadIdx.x;
    const int warp = tid >> 5, lane = tid & 31;
    const int lr = lane >> 2, lc = lane & 3;
    const int r0 = warp * 16 + lr;
    const int r1 = r0 + 8;

    // ldmatrix lane geometry
    const int a_lrow = (lane & 7) + ((lane >> 3) & 1) * 8;   // A-frag rows
    const int a_lcol = ((lane >> 4) & 1) * 4;                // A-frag col half
    const int k_lrow = (lane & 7) + ((lane >> 4) & 1) * 8;   // B-frag rows (n)
    const int k_lcol = ((lane >> 3) & 1) * 4;                // B-frag col half (k)
    const uint32_t sbQ = s2u(Qs);
    const uint32_t sbK = s2u(Ks);

    const float* Qg = g_q + ((size_t)(b * NH + h) * SQ + q0) * DK;
    const float* Kg = g_k + (size_t)(b * NH + h) * SQ * DK;
    const float* Vg = g_v + (size_t)(b * NH + h) * SQ * DK;
    const float* Mg = mask + (size_t)b * SQ * SQ;
    const float* Bg = g_bias + h * NREL;

#pragma unroll
    for (int t = 0; t < 8; t++) {
        int f = tid + t * 256;
        int r = f >> 4, c4 = (f & 15) * 4;
        float4 v = *(const float4*)(Qg + r * DK + c4);
        Qs[r * QP + c4 + 0] = f2tf32(v.x);
        Qs[r * QP + c4 + 1] = f2tf32(v.y);
        Qs[r * QP + c4 + 2] = f2tf32(v.z);
        Qs[r * QP + c4 + 3] = f2tf32(v.w);
    }

    float m0 = -3.0e38f, m1 = -3.0e38f, l0 = 0.f, l1 = 0.f;
    float o[8][4];
#pragma unroll
    for (int nt = 0; nt < 8; nt++)
#pragma unroll
        for (int r = 0; r < 4; r++) o[nt][r] = 0.f;

    const unsigned FULL = 0xffffffffu;
    const int src0 = (lane & 28) | (lc >> 1);
    const int src1 = src0 + 2;
    const bool odd = (lc & 1) != 0;

    for (int k0 = 0; k0 < SQ; k0 += BKV) {
        __syncthreads();
#pragma unroll
        for (int t = 0; t < 4; t++) {
            int f = tid + t * 256;
            int r = f >> 4, c4 = (f & 15) * 4;
            float4 kv = *(const float4*)(Kg + (size_t)(k0 + r) * DK + c4);
            Ks[r * KP + c4 + 0] = f2tf32(kv.x);
            Ks[r * KP + c4 + 1] = f2tf32(kv.y);
            Ks[r * KP + c4 + 2] = f2tf32(kv.z);
            Ks[r * KP + c4 + 3] = f2tf32(kv.w);
            float4 vv = *(const float4*)(Vg + (size_t)(k0 + r) * DK + c4);
            Vs[r * VP + c4 + 0] = f2tf32(vv.x);
            Vs[r * VP + c4 + 1] = f2tf32(vv.y);
            Vs[r * VP + c4 + 2] = f2tf32(vv.z);
            Vs[r * VP + c4 + 3] = f2tf32(vv.w);
        }
        if (tid < 191)
            Bsm[tid] = Bg[k0 - q0 + tid - 127 + (SQ - 1)];
        __syncthreads();

        // S = Q K^T : Q-frag 1 ldmatrix, K-frags 4 ldmatrix (2 nt each)
        float sc[8][4];
#pragma unroll
        for (int nt = 0; nt < 8; nt++)
#pragma unroll
            for (int r = 0; r < 4; r++) sc[nt][r] = 0.f;

#pragma unroll
        for (int ks = 0; ks < 8; ks++) {
            unsigned af[4], kf[4][4];
            ldsm4(af, sbQ + (uint32_t)((warp * 16 + a_lrow) * QP
                                       + ks * 8 + a_lcol) * 4u);
#pragma unroll
            for (int p = 0; p < 4; p++)
                ldsm4(kf[p], sbK + (uint32_t)((p * 16 + k_lrow) * KP
                                              + ks * 8 + k_lcol) * 4u);
#pragma unroll
            for (int p = 0; p < 4; p++) {
                mma_tf32(sc[2 * p + 0], af, &kf[p][0]);
                mma_tf32(sc[2 * p + 1], af, &kf[p][2]);
            }
        }

        {
            int gq0 = q0 + r0, gq1 = q0 + r1;
#pragma unroll
            for (int nt = 0; nt < 8; nt++) {
                int col = nt * 8 + 2 * lc;
                int kg = k0 + col;
                float2 mv0 = *(const float2*)(Mg + (size_t)gq0 * SQ + kg);
                float2 mv1 = *(const float2*)(Mg + (size_t)gq1 * SQ + kg);
                float b00 = Bsm[col - r0 + 127];
                float b01 = Bsm[col + 1 - r0 + 127];
                float b10 = Bsm[col - r1 + 127];
                float b11 = Bsm[col + 1 - r1 + 127];
                sc[nt][0] = sc[nt][0] * 0.125f * mv0.x + (b00 - 10000.f * (1.f - mv0.x));
                sc[nt][1] = sc[nt][1] * 0.125f * mv0.y + (b01 - 10000.f * (1.f - mv0.y));
                sc[nt][2] = sc[nt][2] * 0.125f * mv1.x + (b10 - 10000.f * (1.f - mv1.x));
                sc[nt][3] = sc[nt][3] * 0.125f * mv1.y + (b11 - 10000.f * (1.f - mv1.y));
            }
        }

        float tm0 = -3.0e38f, tm1 = -3.0e38f;
#pragma unroll
        for (int nt = 0; nt < 8; nt++) {
            tm0 = fmaxf(tm0, fmaxf(sc[nt][0], sc[nt][1]));
            tm1 = fmaxf(tm1, fmaxf(sc[nt][2], sc[nt][3]));
        }
        tm0 = fmaxf(tm0, __shfl_xor_sync(FULL, tm0, 1));
        tm0 = fmaxf(tm0, __shfl_xor_sync(FULL, tm0, 2));
        tm1 = fmaxf(tm1, __shfl_xor_sync(FULL, tm1, 1));
        tm1 = fmaxf(tm1, __shfl_xor_sync(FULL, tm1, 2));
        float mn0 = fmaxf(m0, tm0), mn1 = fmaxf(m1, tm1);
        float al0 = __expf(m0 - mn0), al1 = __expf(m1 - mn1);
        m0 = mn0; m1 = mn1;
        float ps0 = 0.f, ps1 = 0.f;
#pragma unroll
        for (int nt = 0; nt < 8; nt++) {
            float e0 = __expf(sc[nt][0] - mn0);
            float e1 = __expf(sc[nt][1] - mn0);
            float e2 = __expf(sc[nt][2] - mn1);
            float e3 = __expf(sc[nt][3] - mn1);
            ps0 += e0 + e1; ps1 += e2 + e3;
            sc[nt][0] = f2tf32(e0); sc[nt][1] = f2tf32(e1);
            sc[nt][2] = f2tf32(e2); sc[nt][3] = f2tf32(e3);
        }
        ps0 += __shfl_xor_sync(FULL, ps0, 1);
        ps0 += __shfl_xor_sync(FULL, ps0, 2);
        ps1 += __shfl_xor_sync(FULL, ps1, 1);
        ps1 += __shfl_xor_sync(FULL, ps1, 2);
        l0 = l0 * al0 + ps0;
        l1 = l1 * al1 + ps1;

#pragma unroll
        for (int nt = 0; nt < 8; nt++) {
            o[nt][0] *= al0; o[nt][1] *= al0;
            o[nt][2] *= al1; o[nt][3] *= al1;
        }

#pragma unroll
        for (int ks = 0; ks < 8; ks++) {
            float t00 = __shfl_sync(FULL, sc[ks][0], src0);
            float t01 = __shfl_sync(FULL, sc[ks][1], src0);
            float t10 = __shfl_sync(FULL, sc[ks][2], src0);
            float t11 = __shfl_sync(FULL, sc[ks][3], src0);
            float u00 = __shfl_sync(FULL, sc[ks][0], src1);
            float u01 = __shfl_sync(FULL, sc[ks][1], src1);
            float u10 = __shfl_sync(FULL, sc[ks][2], src1);
            float u11 = __shfl_sync(FULL, sc[ks][3], src1);
            unsigned af[4];
            af[0] = __float_as_uint(odd ? t01 : t00);
            af[1] = __float_as_uint(odd ? t11 : t10);
            af[2] = __float_as_uint(odd ? u01 : u00);
            af[3] = __float_as_uint(odd ? u11 : u10);
#pragma unroll
            for (int nt = 0; nt < 8; nt++) {
                int d = nt * 8 + lr;
                unsigned bf[2];
                bf[0] = __float_as_uint(Vs[(ks * 8 + lc) * VP + d]);
                bf[1] = __float_as_uint(Vs[(ks * 8 + lc + 4) * VP + d]);
                mma_tf32(o[nt], af, bf);
            }
        }
    }

    {
        float li0 = 1.0f / l0, li1 = 1.0f / l1;
        int gq0 = q0 + r0, gq1 = q0 + r1;
#pragma unroll
        for (int nt = 0; nt < 8; nt++) {
            int d = h * DK + nt * 8 + 2 * lc;
            *(float2*)(g_ctx + (size_t)(b * SQ + gq0) * DMODEL + d) =
                make_float2(o[nt][0] * li0, o[nt][1] * li0);
            *(float2*)(g_ctx + (size_t)(b * SQ + gq1) * DMODEL + d) =
                make_float2(o[nt][2] * li1, o[nt][3] * li1);
        }
    }
}

// ---------------------------------------------------------------------------
extern "C" void kernel_launch(void* const* d_in, const int* in_sizes, int n_in,
                              void* d_out, int out_size) {
    (void)in_sizes; (void)n_in; (void)out_size;
    const float* hidden = (const float*)d_in[0];
    const float* mask   = (const float*)d_in[1];
    const float* Wqkv   = (const float*)d_in[2];
    const float* Wo     = (const float*)d_in[3];
    const float* emb    = (const float*)d_in[4];
    float* out = (float*)d_out;

    bias_kernel<<<16, 256>>>(emb);

    gemm_tc<3072, 0><<<dim3(24, 32), 256>>>(hidden, Wqkv, nullptr);

    const int smem_bytes = (BQ * QP + BKV * KP + BKV * VP + 192) * 4;
    cudaFuncSetAttribute(attn_tc, cudaFuncAttributeMaxDynamicSharedMemorySize,
                         smem_bytes);
    attn_tc<<<dim3(SQ / BQ, NH, BATCH), 256, smem_bytes>>>(mask);

    gemm_tc<1024, 1><<<dim3(8, 32), 256>>>(nullptr, Wo, out);
}